// round 2
// baseline (speedup 1.0000x reference)
#include <cuda_runtime.h>

#define NT 256

// Shared-memory arena layout (floats):
//   [0,     6144)  qkv  (3 x 16 x 128)
//   [6144,  8192)  o    (16 x 128)          (also final-reduce scratch)
//   [8192, 10240)  h    (16 x 128)
//   [10240,18432)  ff   (16 x 512)          (also xs: 16 x 196 padded to stride 200)
//   [18432,20480)  x1/x2 (16 x 128)
#define ARENA_FLOATS 20480
#define OFF_QKV 0
#define OFF_O   6144
#define OFF_H   8192
#define OFF_FF  10240
#define OFF_X1  18432

__device__ __forceinline__ void warp_reduce2(float& s, float& s2) {
    #pragma unroll
    for (int off = 16; off; off >>= 1) {
        s  += __shfl_xor_sync(0xffffffffu, s,  off);
        s2 += __shfl_xor_sync(0xffffffffu, s2, off);
    }
}

// LayerNorm over 16 rows x 128 cols. src/resid/dst are 16x128 (stride 128).
// dst = (dst_add ? dst_add : 0) + LN(src [+ resid]) * g + b
__device__ void lnorm(const float* __restrict__ src, const float* __restrict__ resid,
                      const float* __restrict__ g, const float* __restrict__ b,
                      float* __restrict__ dst, const float* __restrict__ dst_add) {
    int warp = threadIdx.x >> 5, lane = threadIdx.x & 31;
    for (int r = warp; r < 16; r += NT / 32) {
        float v[4]; float s = 0.f, s2 = 0.f;
        #pragma unroll
        for (int i = 0; i < 4; i++) {
            int c = lane + 32 * i;
            float x = src[r * 128 + c];
            if (resid) x += resid[r * 128 + c];
            v[i] = x; s += x; s2 += x * x;
        }
        warp_reduce2(s, s2);
        float m   = s * (1.f / 128.f);
        float var = fmaxf(s2 * (1.f / 128.f) - m * m, 0.f);
        float inv = rsqrtf(var + 1e-5f);
        #pragma unroll
        for (int i = 0; i < 4; i++) {
            int c = lane + 32 * i;
            float val = (v[i] - m) * inv * g[c] + b[c];
            if (dst_add) val += dst_add[r * 128 + c];
            dst[r * 128 + c] = val;
        }
    }
}

// QKV: in (16 x K, smem stride XST) times three (K x 128) weights -> qkv (3 x 16 x 128)
template<int K, int XST>
__device__ void qkv_gemm(const float* __restrict__ in,
                         const float* __restrict__ wq, const float* __restrict__ wk,
                         const float* __restrict__ wv, float* __restrict__ qkv) {
    for (int idx = threadIdx.x; idx < 384; idx += NT) {
        int e = idx & 127, m = idx >> 7;
        const float* W = (m == 0) ? wq : (m == 1) ? wk : wv;
        float acc[16];
        #pragma unroll
        for (int r = 0; r < 16; r++) acc[r] = 0.f;
        #pragma unroll 2
        for (int c = 0; c < K; c += 4) {
            float w0 = W[(c + 0) * 128 + e];
            float w1 = W[(c + 1) * 128 + e];
            float w2 = W[(c + 2) * 128 + e];
            float w3 = W[(c + 3) * 128 + e];
            #pragma unroll
            for (int r = 0; r < 16; r++) {
                float4 x = *reinterpret_cast<const float4*>(&in[r * XST + c]);
                acc[r] += x.x * w0 + x.y * w1 + x.z * w2 + x.w * w3;
            }
        }
        float* op = qkv + m * 2048;
        #pragma unroll
        for (int r = 0; r < 16; r++) op[r * 128 + e] = acc[r];
    }
}

// out (16 x N) = in (16 x K, stride K) @ W (K x N) + bias, optional relu
template<int K>
__device__ void gemm_cols(const float* __restrict__ in, const float* __restrict__ W, int N,
                          const float* __restrict__ bias, float* __restrict__ out, bool relu) {
    for (int e = threadIdx.x; e < N; e += NT) {
        float acc[16];
        #pragma unroll
        for (int r = 0; r < 16; r++) acc[r] = 0.f;
        #pragma unroll 2
        for (int c = 0; c < K; c += 4) {
            float w0 = W[(c + 0) * N + e];
            float w1 = W[(c + 1) * N + e];
            float w2 = W[(c + 2) * N + e];
            float w3 = W[(c + 3) * N + e];
            #pragma unroll
            for (int r = 0; r < 16; r++) {
                float4 x = *reinterpret_cast<const float4*>(&in[r * K + c]);
                acc[r] += x.x * w0 + x.y * w1 + x.z * w2 + x.w * w3;
            }
        }
        float bb = bias[e];
        #pragma unroll
        for (int r = 0; r < 16; r++) {
            float v = acc[r] + bb;
            out[r * N + e] = relu ? fmaxf(v, 0.f) : v;
        }
    }
}

// out (16 x 128) = in (16 x K) @ W (K x 128) + bias; 2 threads per column (8 rows each)
template<int K>
__device__ void gemm_half(const float* __restrict__ in, const float* __restrict__ W,
                          const float* __restrict__ bias, float* __restrict__ out) {
    int e = threadIdx.x & 127, half = threadIdx.x >> 7;
    const float* xr = in + half * 8 * K;
    float acc[8];
    #pragma unroll
    for (int r = 0; r < 8; r++) acc[r] = 0.f;
    #pragma unroll 2
    for (int c = 0; c < K; c += 4) {
        float w0 = W[(c + 0) * 128 + e];
        float w1 = W[(c + 1) * 128 + e];
        float w2 = W[(c + 2) * 128 + e];
        float w3 = W[(c + 3) * 128 + e];
        #pragma unroll
        for (int r = 0; r < 8; r++) {
            float4 x = *reinterpret_cast<const float4*>(&xr[r * K + c]);
            acc[r] += x.x * w0 + x.y * w1 + x.z * w2 + x.w * w3;
        }
    }
    float bb = bias[e];
    #pragma unroll
    for (int r = 0; r < 8; r++) out[(half * 8 + r) * 128 + e] = acc[r] + bb;
}

// Attention: 64 heads, head_dim 2, 16 tokens. qkv = [q|k|v] each 16x128.
__device__ void attention(const float* __restrict__ qkv, float* __restrict__ o) {
    const float* q = qkv;
    const float* k = qkv + 2048;
    const float* v = qkv + 4096;
    const float scale = 0.7071067811865475f; // 1/sqrt(2)
    for (int idx = threadIdx.x; idx < 1024; idx += NT) {
        int hh = idx & 63, qr = idx >> 6;
        float q0 = q[qr * 128 + 2 * hh], q1 = q[qr * 128 + 2 * hh + 1];
        float s[16], mx = -1e30f;
        #pragma unroll
        for (int j = 0; j < 16; j++) {
            s[j] = (q0 * k[j * 128 + 2 * hh] + q1 * k[j * 128 + 2 * hh + 1]) * scale;
            mx = fmaxf(mx, s[j]);
        }
        float sum = 0.f;
        #pragma unroll
        for (int j = 0; j < 16; j++) { s[j] = __expf(s[j] - mx); sum += s[j]; }
        float inv = 1.f / sum;
        float o0 = 0.f, o1 = 0.f;
        #pragma unroll
        for (int j = 0; j < 16; j++) {
            o0 += s[j] * v[j * 128 + 2 * hh];
            o1 += s[j] * v[j * 128 + 2 * hh + 1];
        }
        o[qr * 128 + 2 * hh]     = o0 * inv;
        o[qr * 128 + 2 * hh + 1] = o1 * inv;
    }
}

// One transformer block. in: 16 x K (stride XST). dst = (dst_add?:0) + block(in).
template<int K, int XST>
__device__ void tblock(float* arena, const float* __restrict__ in, bool has_res,
                       const float* __restrict__ wq, const float* __restrict__ wk,
                       const float* __restrict__ wv, const float* __restrict__ wo,
                       const float* __restrict__ bo,
                       const float* __restrict__ ff1, const float* __restrict__ bf1,
                       const float* __restrict__ ff2, const float* __restrict__ bf2,
                       const float* __restrict__ g1, const float* __restrict__ b1,
                       const float* __restrict__ g2, const float* __restrict__ b2,
                       float* __restrict__ dst, const float* __restrict__ dst_add) {
    float* qkv = arena + OFF_QKV;
    float* o   = arena + OFF_O;
    float* h   = arena + OFF_H;
    float* ff  = arena + OFF_FF;

    qkv_gemm<K, XST>(in, wq, wk, wv, qkv);
    __syncthreads();
    attention(qkv, o);
    __syncthreads();
    gemm_half<128>(o, wo, bo, h);          // h <- o @ wo + bo
    __syncthreads();
    lnorm(h, has_res ? in : nullptr, g1, b1, h, nullptr);   // h <- LN(h [+ in])
    __syncthreads();
    gemm_cols<128>(h, ff1, 512, bf1, ff, true);   // ff <- relu(h @ ff1 + bf1)
    __syncthreads();
    gemm_half<512>(ff, ff2, bf2, o);       // o <- ff @ ff2 + bf2
    __syncthreads();
    lnorm(o, h, g2, b2, dst, dst_add);     // dst <- [dst_add +] LN(o + h)
    __syncthreads();
}

__global__ void __launch_bounds__(NT, 2)
encoder_kernel(const float* __restrict__ enc, const float* __restrict__ off,
               const float* __restrict__ b1_wq, const float* __restrict__ b1_wk,
               const float* __restrict__ b1_wv, const float* __restrict__ b1_wo,
               const float* __restrict__ b1_bo,
               const float* __restrict__ b1_ff1, const float* __restrict__ b1_bf1,
               const float* __restrict__ b1_ff2, const float* __restrict__ b1_bf2,
               const float* __restrict__ b1_g1, const float* __restrict__ b1_b1,
               const float* __restrict__ b1_g2, const float* __restrict__ b1_b2,
               const float* __restrict__ b2_wq, const float* __restrict__ b2_wk,
               const float* __restrict__ b2_wv, const float* __restrict__ b2_wo,
               const float* __restrict__ b2_bo,
               const float* __restrict__ b2_ff1, const float* __restrict__ b2_bf1,
               const float* __restrict__ b2_ff2, const float* __restrict__ b2_bf2,
               const float* __restrict__ b2_g1, const float* __restrict__ b2_b1,
               const float* __restrict__ b2_g2, const float* __restrict__ b2_b2,
               const float* __restrict__ wf, const float* __restrict__ bf,
               float* __restrict__ out) {
    extern __shared__ float arena[];
    const int n = blockIdx.x;
    const int b = n >> 7;      // batch
    const int t = n & 127;     // time

    // ---- build windowed input xs: 16 x 196 (stride 200), edge-clamped in time ----
    float* xs = arena + OFF_FF;   // aliases ff region (dead until FF1 of block1)
    for (int i = threadIdx.x; i < 16 * 196; i += NT) {
        int w = i / 196, c = i - w * 196;
        int tc = t + w - 8;
        tc = min(max(tc, 0), 127);
        float val = (c < 112) ? enc[((long)b * 112 + c) * 128 + tc]
                              : off[b * 84 + (c - 112)];
        xs[w * 200 + c] = val;
    }
    __syncthreads();

    float* x1 = arena + OFF_X1;

    // block1: CIN=196 -> 128, no residual into first LN
    tblock<196, 200>(arena, xs, false,
                     b1_wq, b1_wk, b1_wv, b1_wo, b1_bo,
                     b1_ff1, b1_bf1, b1_ff2, b1_bf2,
                     b1_g1, b1_b1, b1_g2, b1_b2,
                     x1, nullptr);

    // block2: 128 -> 128 with residual; x2 = x1 + block2(x1) written in place
    tblock<128, 128>(arena, x1, true,
                     b2_wq, b2_wk, b2_wv, b2_wo, b2_bo,
                     b2_ff1, b2_bf1, b2_ff2, b2_bf2,
                     b2_g1, b2_b1, b2_g2, b2_b2,
                     x1, x1);

    // ---- final projection: y[e] = x2.flat(2048) @ wf[:,e] + bf[e] ----
    int e = threadIdx.x & 127, part = threadIdx.x >> 7;
    float acc = 0.f;
    const float* xv  = x1 + part * 1024;
    const float* wfp = wf + (long)part * 1024 * 128 + e;
    #pragma unroll 2
    for (int c = 0; c < 1024; c += 4) {
        float4 x = *reinterpret_cast<const float4*>(&xv[c]);
        acc += x.x * wfp[(c + 0) * 128] + x.y * wfp[(c + 1) * 128]
             + x.z * wfp[(c + 2) * 128] + x.w * wfp[(c + 3) * 128];
    }
    float* red = arena + OFF_O;
    if (part == 1) red[e] = acc;
    __syncthreads();
    if (part == 0) out[((long)b * 128 + e) * 128 + t] = acc + red[e] + bf[e];
}

extern "C" void kernel_launch(void* const* d_in, const int* in_sizes, int n_in,
                              void* d_out, int out_size) {
    (void)in_sizes; (void)n_in; (void)out_size;
    const float* enc = (const float*)d_in[0];
    const float* off = (const float*)d_in[1];
    const float* p[30];
    for (int i = 0; i < 30; i++) p[i] = (const float*)d_in[i];

    static bool attr_set = false;
    if (!attr_set) {
        cudaFuncSetAttribute(encoder_kernel,
                             cudaFuncAttributeMaxDynamicSharedMemorySize,
                             ARENA_FLOATS * (int)sizeof(float));
        attr_set = true;
    }

    encoder_kernel<<<64 * 128, NT, ARENA_FLOATS * sizeof(float)>>>(
        enc, off,
        p[2], p[3], p[4], p[5], p[6], p[7], p[8], p[9], p[10],
        p[11], p[12], p[13], p[14],
        p[15], p[16], p[17], p[18], p[19], p[20], p[21], p[22], p[23],
        p[24], p[25], p[26], p[27],
        p[28], p[29],
        (float*)d_out);
}

// round 3
// speedup vs baseline: 2.5864x; 2.5864x over previous
#include <cuda_runtime.h>

#define NT 256

// ---------------- fragment-linear tf32 weight scratch ----------------
// 12 matrices packed as m16n8k8 B-fragments:
//   block index (kt*NTW + nt), inside block: lane*2 + reg  (uint32 each)
#define FRAG_TOTAL 420864
__device__ unsigned int g_wfrag[FRAG_TOTAL];

// region offsets (elements)
#define WF_QKV1  0        // 3 x 25600  (K=196 pad 200, N=128)
#define WF_WO1   76800    // 16384
#define WF_FF1_1 93184    // 65536
#define WF_FF2_1 158720   // 65536
#define WF_QKV2  224256   // 3 x 16384
#define WF_WO2   273408   // 16384
#define WF_FF1_2 289792   // 65536
#define WF_FF2_2 355328   // 65536

__global__ void prep_weights(const float* __restrict__ wq1, const float* __restrict__ wk1,
                             const float* __restrict__ wv1, const float* __restrict__ wo1,
                             const float* __restrict__ f11, const float* __restrict__ f21,
                             const float* __restrict__ wq2, const float* __restrict__ wk2,
                             const float* __restrict__ wv2, const float* __restrict__ wo2,
                             const float* __restrict__ f12, const float* __restrict__ f22) {
    int e = blockIdx.x * blockDim.x + threadIdx.x;
    if (e >= FRAG_TOTAL) return;
    const int offs[13] = {0,25600,51200,76800,93184,158720,224256,240640,257024,273408,289792,355328,420864};
    const int Kr[12]   = {196,196,196,128,128,512,128,128,128,128,128,512};
    const int Nn[12]   = {128,128,128,128,512,128,128,128,128,128,512,128};
    int m = 0;
    while (e >= offs[m + 1]) m++;
    const float* W =
        m==0?wq1: m==1?wk1: m==2?wv1: m==3?wo1: m==4?f11: m==5?f21:
        m==6?wq2: m==7?wk2: m==8?wv2: m==9?wo2: m==10?f12: f22;
    int l = e - offs[m];
    int blk = l >> 6, li = l & 63;
    int lane = li >> 1, rr = li & 1;
    int N = Nn[m], NTW = N >> 3;
    int kt = blk / NTW, nt = blk - kt * NTW;
    int k = kt * 8 + (lane & 3) + 4 * rr;
    int n = nt * 8 + (lane >> 2);
    float v = (k < Kr[m]) ? W[k * N + n] : 0.f;
    unsigned int u;
    asm("cvt.rna.tf32.f32 %0, %1;" : "=r"(u) : "f"(v));
    g_wfrag[e] = u;
}

// ---------------- shared arena (floats) ----------------
// strides: 132 (16x128 tiles), 516 (16x512 ff), 204 (16x200 xs). All ≡ 4 or 12 mod 32
// so m16n8k8 A-fragment LDS.32 loads are bank-conflict free.
#define OFF_BIG 0          // xs (16x204 used) / ff (16x516) : 8256
#define OFF_Q   8256       // 16x132
#define OFF_K   10368
#define OFF_V   12480
#define OFF_O   14592
#define OFF_H   16704
#define OFF_X1  18816
#define ARENA_FLOATS 20928

__device__ __forceinline__ void mma_tf32(float* d, unsigned a0, unsigned a1,
                                         unsigned a2, unsigned a3,
                                         unsigned b0, unsigned b1) {
    asm volatile("mma.sync.aligned.m16n8k8.row.col.f32.tf32.tf32.f32 "
                 "{%0,%1,%2,%3}, {%4,%5,%6,%7}, {%8,%9}, {%0,%1,%2,%3};"
                 : "+f"(d[0]), "+f"(d[1]), "+f"(d[2]), "+f"(d[3])
                 : "r"(a0), "r"(a1), "r"(a2), "r"(a3), "r"(b0), "r"(b1));
}

// out(16 x NTW*8) = A(16 x KT*8) @ W + bias  [relu]
template<int KT, int NTS, int NTW, bool RELU>
__device__ void mma_stage(const float* __restrict__ A, int SA,
                          const unsigned int* __restrict__ Wf,
                          const float* __restrict__ bias,
                          float* __restrict__ out, int SO) {
    const int warp = threadIdx.x >> 5, lane = threadIdx.x & 31;
    const int r = lane >> 2, c = lane & 3;
    const uint2* __restrict__ W2 = reinterpret_cast<const uint2*>(Wf);
    float acc[NTS][4];
    #pragma unroll
    for (int i = 0; i < NTS; i++)
        acc[i][0] = acc[i][1] = acc[i][2] = acc[i][3] = 0.f;
    const float* Ap = A + r * SA + c;
    #pragma unroll 2
    for (int kt = 0; kt < KT; kt++) {
        unsigned a0 = __float_as_uint(Ap[kt * 8]);
        unsigned a1 = __float_as_uint(Ap[kt * 8 + 8 * SA]);
        unsigned a2 = __float_as_uint(Ap[kt * 8 + 4]);
        unsigned a3 = __float_as_uint(Ap[kt * 8 + 4 + 8 * SA]);
        #pragma unroll
        for (int i = 0; i < NTS; i++) {
            int nt = warp + 8 * i;
            uint2 b = W2[(kt * NTW + nt) * 32 + lane];
            mma_tf32(acc[i], a0, a1, a2, a3, b.x, b.y);
        }
    }
    #pragma unroll
    for (int i = 0; i < NTS; i++) {
        int n0 = (warp + 8 * i) * 8 + 2 * c;
        float b0 = bias ? bias[n0] : 0.f;
        float b1 = bias ? bias[n0 + 1] : 0.f;
        float v0 = acc[i][0] + b0, v1 = acc[i][1] + b1;
        float v2 = acc[i][2] + b0, v3 = acc[i][3] + b1;
        if (RELU) {
            v0 = fmaxf(v0, 0.f); v1 = fmaxf(v1, 0.f);
            v2 = fmaxf(v2, 0.f); v3 = fmaxf(v3, 0.f);
        }
        out[r * SO + n0] = v0;       out[r * SO + n0 + 1] = v1;
        out[(r + 8) * SO + n0] = v2; out[(r + 8) * SO + n0 + 1] = v3;
    }
}

// q,k,v (each 16x128 @ stride 132) from A(16 x KT*8); Wf = 3 regions of KT*1024
template<int KT>
__device__ void mma_qkv(const float* __restrict__ A, int SA,
                        const unsigned int* __restrict__ Wf,
                        float* __restrict__ qkv) {
    const int warp = threadIdx.x >> 5, lane = threadIdx.x & 31;
    const int r = lane >> 2, c = lane & 3;
    float acc[6][4];
    #pragma unroll
    for (int i = 0; i < 6; i++)
        acc[i][0] = acc[i][1] = acc[i][2] = acc[i][3] = 0.f;
    const float* Ap = A + r * SA + c;
    #pragma unroll 2
    for (int kt = 0; kt < KT; kt++) {
        unsigned a0 = __float_as_uint(Ap[kt * 8]);
        unsigned a1 = __float_as_uint(Ap[kt * 8 + 8 * SA]);
        unsigned a2 = __float_as_uint(Ap[kt * 8 + 4]);
        unsigned a3 = __float_as_uint(Ap[kt * 8 + 4 + 8 * SA]);
        #pragma unroll
        for (int i = 0; i < 6; i++) {
            int ntg = warp + 8 * i;
            int m = ntg >> 4, ntl = ntg & 15;
            const uint2* W2 = reinterpret_cast<const uint2*>(Wf + m * (KT * 1024));
            uint2 b = W2[(kt * 16 + ntl) * 32 + lane];
            mma_tf32(acc[i], a0, a1, a2, a3, b.x, b.y);
        }
    }
    #pragma unroll
    for (int i = 0; i < 6; i++) {
        int ntg = warp + 8 * i;
        int m = ntg >> 4, ntl = ntg & 15;
        int n0 = ntl * 8 + 2 * c;
        float* op = qkv + m * 2112;
        op[r * 132 + n0] = acc[i][0];       op[r * 132 + n0 + 1] = acc[i][1];
        op[(r + 8) * 132 + n0] = acc[i][2]; op[(r + 8) * 132 + n0 + 1] = acc[i][3];
    }
}

__device__ __forceinline__ void warp_reduce2(float& s, float& s2) {
    #pragma unroll
    for (int off = 16; off; off >>= 1) {
        s  += __shfl_xor_sync(0xffffffffu, s,  off);
        s2 += __shfl_xor_sync(0xffffffffu, s2, off);
    }
}

// LayerNorm over 16 rows x 128 cols (all buffers stride 132)
__device__ void lnorm(const float* __restrict__ src, const float* __restrict__ resid,
                      const float* __restrict__ g, const float* __restrict__ b,
                      float* __restrict__ dst, const float* __restrict__ dst_add) {
    int warp = threadIdx.x >> 5, lane = threadIdx.x & 31;
    for (int r = warp; r < 16; r += NT / 32) {
        float v[4]; float s = 0.f, s2 = 0.f;
        #pragma unroll
        for (int i = 0; i < 4; i++) {
            int c = lane + 32 * i;
            float x = src[r * 132 + c];
            if (resid) x += resid[r * 132 + c];
            v[i] = x; s += x; s2 += x * x;
        }
        warp_reduce2(s, s2);
        float m   = s * (1.f / 128.f);
        float var = fmaxf(s2 * (1.f / 128.f) - m * m, 0.f);
        float inv = rsqrtf(var + 1e-5f);
        #pragma unroll
        for (int i = 0; i < 4; i++) {
            int c = lane + 32 * i;
            float val = (v[i] - m) * inv * g[c] + b[c];
            if (dst_add) val += dst_add[r * 132 + c];
            dst[r * 132 + c] = val;
        }
    }
}

// 64 heads, head_dim 2, 16 tokens; q/k/v at stride 132
__device__ void attention(const float* __restrict__ qkv, float* __restrict__ o) {
    const float* q = qkv;
    const float* k = qkv + 2112;
    const float* v = qkv + 4224;
    const float scale = 0.7071067811865475f;
    for (int idx = threadIdx.x; idx < 1024; idx += NT) {
        int hh = idx & 63, qr = idx >> 6;
        float q0 = q[qr * 132 + 2 * hh], q1 = q[qr * 132 + 2 * hh + 1];
        float s[16], mx = -1e30f;
        #pragma unroll
        for (int j = 0; j < 16; j++) {
            s[j] = (q0 * k[j * 132 + 2 * hh] + q1 * k[j * 132 + 2 * hh + 1]) * scale;
            mx = fmaxf(mx, s[j]);
        }
        float sum = 0.f;
        #pragma unroll
        for (int j = 0; j < 16; j++) { s[j] = __expf(s[j] - mx); sum += s[j]; }
        float inv = 1.f / sum;
        float o0 = 0.f, o1 = 0.f;
        #pragma unroll
        for (int j = 0; j < 16; j++) {
            o0 += s[j] * v[j * 132 + 2 * hh];
            o1 += s[j] * v[j * 132 + 2 * hh + 1];
        }
        o[qr * 132 + 2 * hh]     = o0 * inv;
        o[qr * 132 + 2 * hh + 1] = o1 * inv;
    }
}

__global__ void __launch_bounds__(NT, 2)
encoder_kernel(const float* __restrict__ enc, const float* __restrict__ off,
               const float* __restrict__ b1_bo,
               const float* __restrict__ b1_bf1, const float* __restrict__ b1_bf2,
               const float* __restrict__ b1_g1, const float* __restrict__ b1_b1,
               const float* __restrict__ b1_g2, const float* __restrict__ b1_b2,
               const float* __restrict__ b2_bo,
               const float* __restrict__ b2_bf1, const float* __restrict__ b2_bf2,
               const float* __restrict__ b2_g1, const float* __restrict__ b2_b1,
               const float* __restrict__ b2_g2, const float* __restrict__ b2_b2,
               const float* __restrict__ wf, const float* __restrict__ bf,
               float* __restrict__ out) {
    extern __shared__ float arena[];
    const unsigned int* WF = g_wfrag;
    const int n = blockIdx.x;
    const int b = n >> 7;
    const int t = n & 127;

    // ---- windowed input xs: 16 x 200 (stride 204), cols 196..199 zero ----
    float* xs = arena + OFF_BIG;
    for (int i = threadIdx.x; i < 16 * 200; i += NT) {
        int w = i / 200, c = i - w * 200;
        int tc = t + w - 8;
        tc = min(max(tc, 0), 127);
        float val = (c < 112) ? enc[((long)b * 112 + c) * 128 + tc]
                  : (c < 196) ? off[b * 84 + (c - 112)]
                  : 0.f;
        xs[w * 204 + c] = val;
    }
    __syncthreads();

    float* q  = arena + OFF_Q;
    float* o  = arena + OFF_O;
    float* h  = arena + OFF_H;
    float* ff = arena + OFF_BIG;
    float* x1 = arena + OFF_X1;

    // ================= block 1 (CIN=196->128, no residual) =================
    mma_qkv<25>(xs, 204, WF + WF_QKV1, q);
    __syncthreads();
    attention(q, o);
    __syncthreads();
    mma_stage<16, 2, 16, false>(o, 132, WF + WF_WO1, b1_bo, h, 132);
    __syncthreads();
    lnorm(h, nullptr, b1_g1, b1_b1, h, nullptr);
    __syncthreads();
    mma_stage<16, 8, 64, true>(h, 132, WF + WF_FF1_1, b1_bf1, ff, 516);
    __syncthreads();
    mma_stage<64, 2, 16, false>(ff, 516, WF + WF_FF2_1, b1_bf2, o, 132);
    __syncthreads();
    lnorm(o, h, b1_g2, b1_b2, x1, nullptr);
    __syncthreads();

    // ================= block 2 (128->128, residual; x2 = x1 + blk(x1)) =====
    mma_qkv<16>(x1, 132, WF + WF_QKV2, q);
    __syncthreads();
    attention(q, o);
    __syncthreads();
    mma_stage<16, 2, 16, false>(o, 132, WF + WF_WO2, b2_bo, h, 132);
    __syncthreads();
    lnorm(h, x1, b2_g1, b2_b1, h, nullptr);
    __syncthreads();
    mma_stage<16, 8, 64, true>(h, 132, WF + WF_FF1_2, b2_bf1, ff, 516);
    __syncthreads();
    mma_stage<64, 2, 16, false>(ff, 516, WF + WF_FF2_2, b2_bf2, o, 132);
    __syncthreads();
    lnorm(o, h, b2_g2, b2_b2, x1, x1);
    __syncthreads();

    // ---- final projection: y[e] = x2.flat(2048) @ wf[:,e] + bf[e] ----
    int e = threadIdx.x & 127, part = threadIdx.x >> 7;
    float acc = 0.f;
    #pragma unroll
    for (int w = part * 8; w < part * 8 + 8; w++) {
        const float* xrow = x1 + w * 132;
        const float* wfp  = wf + ((long)w * 128) * 128 + e;
        #pragma unroll 2
        for (int cc = 0; cc < 128; cc += 4) {
            float4 x = *reinterpret_cast<const float4*>(&xrow[cc]);
            acc += x.x * wfp[(cc + 0) * 128] + x.y * wfp[(cc + 1) * 128]
                 + x.z * wfp[(cc + 2) * 128] + x.w * wfp[(cc + 3) * 128];
        }
    }
    float* red = arena + OFF_O;
    if (part == 1) red[e] = acc;
    __syncthreads();
    if (part == 0) out[((long)b * 128 + e) * 128 + t] = acc + red[e] + bf[e];
}

extern "C" void kernel_launch(void* const* d_in, const int* in_sizes, int n_in,
                              void* d_out, int out_size) {
    (void)in_sizes; (void)n_in; (void)out_size;
    const float* p[30];
    for (int i = 0; i < 30; i++) p[i] = (const float*)d_in[i];

    static bool attr_set = false;
    if (!attr_set) {
        cudaFuncSetAttribute(encoder_kernel,
                             cudaFuncAttributeMaxDynamicSharedMemorySize,
                             ARENA_FLOATS * (int)sizeof(float));
        attr_set = true;
    }

    // weight fragment prep (runs every launch; graph-capturable)
    prep_weights<<<(FRAG_TOTAL + 255) / 256, 256>>>(
        p[2], p[3], p[4], p[5],          // b1 wq wk wv wo
        p[7], p[9],                      // b1 ff1 ff2
        p[15], p[16], p[17], p[18],      // b2 wq wk wv wo
        p[20], p[22]);                   // b2 ff1 ff2

    encoder_kernel<<<64 * 128, NT, ARENA_FLOATS * sizeof(float)>>>(
        p[0], p[1],
        p[6],  p[8],  p[10], p[11], p[12], p[13], p[14],   // b1 biases/LN
        p[19], p[21], p[23], p[24], p[25], p[26], p[27],   // b2 biases/LN
        p[28], p[29],
        (float*)d_out);
}

// round 5
// speedup vs baseline: 4.3821x; 1.6943x over previous
#include <cuda_runtime.h>

#define NT 512

// ---------------- fragment-linear tf32 weight scratch ----------------
// m16n8k8 B-fragments, round-2 verified layout:
//   uint index = (kt*NTW + nt)*64 + lane*2 + reg
//   k = kt*8 + (lane&3) + 4*reg ; n = nt*8 + (lane>>2)
#define FRAG_TOTAL 683008
__device__ __align__(16) unsigned int g_wfrag[FRAG_TOTAL];

#define WFQ1 0
#define WFK1 25600
#define WFV1 51200
#define WFO1 76800
#define WF11 93184
#define WF21 158720
#define WFQ2 224256
#define WFK2 240640
#define WFV2 257024
#define WFO2 273408
#define WF12 289792
#define WF22 355328
#define WFWF 420864

__global__ void prep_weights(const float* __restrict__ q1, const float* __restrict__ k1,
                             const float* __restrict__ v1, const float* __restrict__ o1,
                             const float* __restrict__ f11, const float* __restrict__ f21,
                             const float* __restrict__ q2, const float* __restrict__ k2,
                             const float* __restrict__ v2, const float* __restrict__ o2,
                             const float* __restrict__ f12, const float* __restrict__ f22,
                             const float* __restrict__ wf) {
    int e = blockIdx.x * blockDim.x + threadIdx.x;
    if (e >= FRAG_TOTAL) return;
    const int offs[14] = {0,25600,51200,76800,93184,158720,224256,240640,257024,
                          273408,289792,355328,420864,683008};
    const int Kr[13] = {196,196,196,128,128,512,128,128,128,128,128,512,2048};
    const int Nn[13] = {128,128,128,128,512,128,128,128,128,128,512,128,128};
    int m = 0;
    while (e >= offs[m + 1]) m++;
    const float* W =
        m==0?q1: m==1?k1: m==2?v1: m==3?o1: m==4?f11: m==5?f21:
        m==6?q2: m==7?k2: m==8?v2: m==9?o2: m==10?f12: m==11?f22: wf;
    int l = e - offs[m];
    int blk = l >> 6, li = l & 63;
    int lane = li >> 1, rr = li & 1;
    int N = Nn[m], NTW = N >> 3;
    int kt = blk / NTW, nt = blk - kt * NTW;
    int k = kt * 8 + (lane & 3) + 4 * rr;
    int n = nt * 8 + (lane >> 2);
    float v = (k < Kr[m]) ? W[k * N + n] : 0.f;
    unsigned int u;
    asm("cvt.rna.tf32.f32 %0, %1;" : "=r"(u) : "f"(v));
    g_wfrag[e] = u;
}

// ---------------- shared arena (floats) ----------------
// strides mod 32 ∈ {4,12} -> conflict-free scalar A-fragment LDS
#define ST_X   132
#define ST_XS  204
#define ST_FF  260
#define ST_F   2052
#define S_X2F  0        // 4 x 2052 real rows (frag reads extend into later buffers: finite garbage, discarded)
#define S_O    8208     // 64 x 132
#define S_H    16656    // 64 x 132
#define S_X1   25104    // 64 x 132
#define S_FFH  33552    // 64 x 260 (xs 64 x 204 aliases here)
#define ARENA_FLOATS 50192

__device__ __forceinline__ void mma8(float* d, float a0, float a1, float a2, float a3,
                                     unsigned b0, unsigned b1) {
    asm volatile("mma.sync.aligned.m16n8k8.row.col.f32.tf32.tf32.f32 "
                 "{%0,%1,%2,%3}, {%4,%5,%6,%7}, {%8,%9}, {%0,%1,%2,%3};"
                 : "+f"(d[0]), "+f"(d[1]), "+f"(d[2]), "+f"(d[3])
                 : "r"(__float_as_uint(a0)), "r"(__float_as_uint(a1)),
                   "r"(__float_as_uint(a2)), "r"(__float_as_uint(a3)),
                   "r"(b0), "r"(b1));
}

__device__ __forceinline__ void warp_reduce2(float& s, float& s2) {
    #pragma unroll
    for (int off = 16; off; off >>= 1) {
        s  += __shfl_xor_sync(0xffffffffu, s,  off);
        s2 += __shfl_xor_sync(0xffffffffu, s2, off);
    }
}

// LayerNorm over 64 rows x 128 cols (stride ST_X buffers).
// If dstFlat: write (val [+dst_add]) to dstFlat[s*ST_F + w*128 + col] (s=row>>4,w=row&15).
__device__ void lnorm64(const float* __restrict__ src, const float* __restrict__ resid,
                        const float* __restrict__ g, const float* __restrict__ bta,
                        float* __restrict__ dst, const float* __restrict__ dst_add,
                        float* __restrict__ dstFlat) {
    int warp = threadIdx.x >> 5, lane = threadIdx.x & 31;
    #pragma unroll
    for (int rr = 0; rr < 4; rr++) {
        int row = warp + rr * 16;
        float v[4]; float s = 0.f, s2 = 0.f;
        #pragma unroll
        for (int i = 0; i < 4; i++) {
            int col = lane + 32 * i;
            float x = src[row * ST_X + col];
            if (resid) x += resid[row * ST_X + col];
            v[i] = x; s += x; s2 += x * x;
        }
        warp_reduce2(s, s2);
        float m   = s * (1.f / 128.f);
        float var = fmaxf(s2 * (1.f / 128.f) - m * m, 0.f);
        float inv = rsqrtf(var + 1e-5f);
        #pragma unroll
        for (int i = 0; i < 4; i++) {
            int col = lane + 32 * i;
            float val = (v[i] - m) * inv * g[col] + bta[col];
            if (dst_add) val += dst_add[row * ST_X + col];
            if (dstFlat) {
                int sq = row >> 4, w = row & 15;
                dstFlat[sq * ST_F + w * 128 + col] = val;
            } else {
                dst[row * ST_X + col] = val;
            }
        }
    }
}

// One transformer block over 4 sequences (64 rows).
template<int KT, int SX>
__device__ void run_block(float* arena, const float* __restrict__ X,
                          const float* __restrict__ resid,
                          const uint2* __restrict__ Fq, const uint2* __restrict__ Fk,
                          const uint2* __restrict__ Fv, const uint2* __restrict__ Fo,
                          const uint2* __restrict__ F1, const uint2* __restrict__ F2,
                          const float* __restrict__ bo, const float* __restrict__ bf1,
                          const float* __restrict__ bf2,
                          const float* __restrict__ g1, const float* __restrict__ b1v,
                          const float* __restrict__ g2, const float* __restrict__ b2v,
                          float* __restrict__ dst, float* __restrict__ dstFlat) {
    const int warp = threadIdx.x >> 5, lane = threadIdx.x & 31;
    const int r = lane >> 2, c = lane & 3;
    float* o   = arena + S_O;
    float* h   = arena + S_H;
    float* ffh = arena + S_FFH;

    // ---- QKV (warp = nt, 4 seqs, q/k/v share A) + register attention ----
    {
        float aq[4][4] = {}, ak[4][4] = {}, av[4][4] = {};
        const float* Ap = X + r * SX + c;
        for (int kt = 0; kt < KT; kt++) {
            uint2 bq = Fq[(kt * 16 + warp) * 32 + lane];
            uint2 bk = Fk[(kt * 16 + warp) * 32 + lane];
            uint2 bv = Fv[(kt * 16 + warp) * 32 + lane];
            #pragma unroll
            for (int s = 0; s < 4; s++) {
                const float* As = Ap + s * 16 * SX + kt * 8;
                float a0 = As[0], a1 = As[8 * SX], a2 = As[4], a3 = As[4 + 8 * SX];
                mma8(aq[s], a0, a1, a2, a3, bq.x, bq.y);
                mma8(ak[s], a0, a1, a2, a3, bk.x, bk.y);
                mma8(av[s], a0, a1, a2, a3, bv.x, bv.y);
            }
        }
        // attention: thread owns head hh = warp*4 + c, q rows r and r+8, seq s
        const float scale = 0.70710678118654752f;
        #pragma unroll
        for (int s = 0; s < 4; s++) {
            float sumA = 0.f, sumB = 0.f;
            float oA0 = 0.f, oA1 = 0.f, oB0 = 0.f, oB1 = 0.f;
            #pragma unroll
            for (int rp = 0; rp < 8; rp++) {
                int src = rp * 4 + c;
                float k00 = __shfl_sync(0xffffffffu, ak[s][0], src);
                float k01 = __shfl_sync(0xffffffffu, ak[s][1], src);
                float k10 = __shfl_sync(0xffffffffu, ak[s][2], src);
                float k11 = __shfl_sync(0xffffffffu, ak[s][3], src);
                float v00 = __shfl_sync(0xffffffffu, av[s][0], src);
                float v01 = __shfl_sync(0xffffffffu, av[s][1], src);
                float v10 = __shfl_sync(0xffffffffu, av[s][2], src);
                float v11 = __shfl_sync(0xffffffffu, av[s][3], src);
                float eA0 = __expf((aq[s][0] * k00 + aq[s][1] * k01) * scale);
                float eA1 = __expf((aq[s][0] * k10 + aq[s][1] * k11) * scale);
                float eB0 = __expf((aq[s][2] * k00 + aq[s][3] * k01) * scale);
                float eB1 = __expf((aq[s][2] * k10 + aq[s][3] * k11) * scale);
                sumA += eA0 + eA1; sumB += eB0 + eB1;
                oA0 += eA0 * v00 + eA1 * v10; oA1 += eA0 * v01 + eA1 * v11;
                oB0 += eB0 * v00 + eB1 * v10; oB1 += eB0 * v01 + eB1 * v11;
            }
            int n0 = warp * 8 + 2 * c;
            float iA = 1.f / sumA, iB = 1.f / sumB;
            *(float2*)(o + (s * 16 + r) * ST_X + n0)     = make_float2(oA0 * iA, oA1 * iA);
            *(float2*)(o + (s * 16 + r + 8) * ST_X + n0) = make_float2(oB0 * iB, oB1 * iB);
        }
    }
    __syncthreads();

    const int sp = warp >> 3, q = warp & 7;   // 2-seq group, nt group

    // ---- WO: warp = (2 nt, 2 seq) ----
    {
        float acc[2][2][4] = {};
        const float* Ap = o + (sp * 32 + r) * ST_X + c;
        for (int kt = 0; kt < 16; kt++) {
            uint2 bb0 = Fo[(kt * 16 + 2 * q)     * 32 + lane];
            uint2 bb1 = Fo[(kt * 16 + 2 * q + 1) * 32 + lane];
            #pragma unroll
            for (int s = 0; s < 2; s++) {
                const float* As = Ap + s * 16 * ST_X + kt * 8;
                float a0 = As[0], a1 = As[8 * ST_X], a2 = As[4], a3 = As[4 + 8 * ST_X];
                mma8(acc[0][s], a0, a1, a2, a3, bb0.x, bb0.y);
                mma8(acc[1][s], a0, a1, a2, a3, bb1.x, bb1.y);
            }
        }
        #pragma unroll
        for (int j = 0; j < 2; j++) {
            int n0 = (2 * q + j) * 8 + 2 * c;
            float2 bb = *(const float2*)(bo + n0);
            #pragma unroll
            for (int s = 0; s < 2; s++) {
                int row = (sp * 2 + s) * 16 + r;
                *(float2*)(h + row * ST_X + n0)       = make_float2(acc[j][s][0] + bb.x, acc[j][s][1] + bb.y);
                *(float2*)(h + (row + 8) * ST_X + n0) = make_float2(acc[j][s][2] + bb.x, acc[j][s][3] + bb.y);
            }
        }
    }
    __syncthreads();

    lnorm64(h, resid, g1, b1v, h, nullptr, nullptr);
    __syncthreads();

    // ---- FF in two N=256 halves; FF2 accumulates across halves ----
    float accF2[2][2][4] = {};
    #pragma unroll
    for (int half = 0; half < 2; half++) {
        // FF1: warp = (4 nt local, 2 seq)
        {
            float a1a[4][2][4] = {};
            const float* Ap = h + (sp * 32 + r) * ST_X + c;
            for (int kt = 0; kt < 16; kt++) {
                uint2 bb[4];
                #pragma unroll
                for (int j = 0; j < 4; j++)
                    bb[j] = F1[(kt * 64 + half * 32 + q * 4 + j) * 32 + lane];
                #pragma unroll
                for (int s = 0; s < 2; s++) {
                    const float* As = Ap + s * 16 * ST_X + kt * 8;
                    float a0 = As[0], a1 = As[8 * ST_X], a2 = As[4], a3 = As[4 + 8 * ST_X];
                    #pragma unroll
                    for (int j = 0; j < 4; j++)
                        mma8(a1a[j][s], a0, a1, a2, a3, bb[j].x, bb[j].y);
                }
            }
            #pragma unroll
            for (int j = 0; j < 4; j++) {
                int n0l = (q * 4 + j) * 8 + 2 * c;
                float2 bb = *(const float2*)(bf1 + half * 256 + n0l);
                #pragma unroll
                for (int s = 0; s < 2; s++) {
                    int row = (sp * 2 + s) * 16 + r;
                    *(float2*)(ffh + row * ST_FF + n0l) =
                        make_float2(fmaxf(a1a[j][s][0] + bb.x, 0.f), fmaxf(a1a[j][s][1] + bb.y, 0.f));
                    *(float2*)(ffh + (row + 8) * ST_FF + n0l) =
                        make_float2(fmaxf(a1a[j][s][2] + bb.x, 0.f), fmaxf(a1a[j][s][3] + bb.y, 0.f));
                }
            }
        }
        __syncthreads();
        // FF2: warp = (2 nt, 2 seq), local KT=32
        {
            const float* Ap = ffh + (sp * 32 + r) * ST_FF + c;
            for (int ktl = 0; ktl < 32; ktl++) {
                int kt = half * 32 + ktl;
                uint2 bb0 = F2[(kt * 16 + 2 * q)     * 32 + lane];
                uint2 bb1 = F2[(kt * 16 + 2 * q + 1) * 32 + lane];
                #pragma unroll
                for (int s = 0; s < 2; s++) {
                    const float* As = Ap + s * 16 * ST_FF + ktl * 8;
                    float a0 = As[0], a1 = As[8 * ST_FF], a2 = As[4], a3 = As[4 + 8 * ST_FF];
                    mma8(accF2[0][s], a0, a1, a2, a3, bb0.x, bb0.y);
                    mma8(accF2[1][s], a0, a1, a2, a3, bb1.x, bb1.y);
                }
            }
        }
        __syncthreads();
    }
    // write FF2 result to o
    #pragma unroll
    for (int j = 0; j < 2; j++) {
        int n0 = (2 * q + j) * 8 + 2 * c;
        float2 bb = *(const float2*)(bf2 + n0);
        #pragma unroll
        for (int s = 0; s < 2; s++) {
            int row = (sp * 2 + s) * 16 + r;
            *(float2*)(o + row * ST_X + n0)       = make_float2(accF2[j][s][0] + bb.x, accF2[j][s][1] + bb.y);
            *(float2*)(o + (row + 8) * ST_X + n0) = make_float2(accF2[j][s][2] + bb.x, accF2[j][s][3] + bb.y);
        }
    }
    __syncthreads();

    lnorm64(o, h, g2, b2v, dst, resid, dstFlat);
    __syncthreads();
}

__global__ void __launch_bounds__(NT, 1)
encoder_kernel(const float* __restrict__ enc, const float* __restrict__ off,
               const float* __restrict__ b1_bo, const float* __restrict__ b1_bf1,
               const float* __restrict__ b1_bf2,
               const float* __restrict__ b1_g1, const float* __restrict__ b1_b1,
               const float* __restrict__ b1_g2, const float* __restrict__ b1_b2,
               const float* __restrict__ b2_bo, const float* __restrict__ b2_bf1,
               const float* __restrict__ b2_bf2,
               const float* __restrict__ b2_g1, const float* __restrict__ b2_b1,
               const float* __restrict__ b2_g2, const float* __restrict__ b2_b2,
               const float* __restrict__ bf, float* __restrict__ out) {
    extern __shared__ float arena[];
    const int tid = threadIdx.x;
    const int warp = tid >> 5, lane = tid & 31;
    const int r = lane >> 2, c = lane & 3;
    const int b = blockIdx.x >> 5;
    const int t0 = (blockIdx.x & 31) << 2;

    float* x2f = arena + S_X2F;
    float* x1  = arena + S_X1;
    float* xs  = arena + S_FFH;   // aliases ffh (dead until FF1)

    // ---- windowed input: 4 seqs x 16 x 200 (stride 204), cols 196..199 zero ----
    for (int i = tid; i < 64 * 200; i += NT) {
        int row = i / 200, cc = i - row * 200;
        int s = row >> 4, w = row & 15;
        int tc = min(max(t0 + s + w - 8, 0), 127);
        float val = 0.f;
        if (cc < 112)      val = enc[((long)b * 112 + cc) * 128 + tc];
        else if (cc < 196) val = off[b * 84 + (cc - 112)];
        xs[row * ST_XS + cc] = val;
    }
    __syncthreads();

    const unsigned* G = g_wfrag;
    // block 1: CIN=196(pad200) -> 128, no residual; dst = x1
    run_block<25, ST_XS>(arena, xs, nullptr,
                         (const uint2*)(G + WFQ1), (const uint2*)(G + WFK1),
                         (const uint2*)(G + WFV1), (const uint2*)(G + WFO1),
                         (const uint2*)(G + WF11), (const uint2*)(G + WF21),
                         b1_bo, b1_bf1, b1_bf2, b1_g1, b1_b1, b1_g2, b1_b2,
                         x1, nullptr);

    // block 2: 128 -> 128 with residual; x2 = x1 + blk(x1), written FLAT into x2f
    run_block<16, ST_X>(arena, x1, x1,
                        (const uint2*)(G + WFQ2), (const uint2*)(G + WFK2),
                        (const uint2*)(G + WFV2), (const uint2*)(G + WFO2),
                        (const uint2*)(G + WF12), (const uint2*)(G + WF22),
                        b2_bo, b2_bf1, b2_bf2, b2_g1, b2_b1, b2_g2, b2_b2,
                        nullptr, x2f);

    // ---- final projection as MMA: C(16x128) = x2f(16x2048) @ wf ----
    {
        const uint2* Fw = (const uint2*)(G + WFWF);
        const int kh = warp >> 3, q = warp & 7;
        float acc[2][4] = {};
        const float* Ap = x2f + r * ST_F + c;
        for (int ktl = 0; ktl < 128; ktl++) {
            int kt = kh * 128 + ktl;
            uint2 bb0 = Fw[(kt * 16 + 2 * q)     * 32 + lane];
            uint2 bb1 = Fw[(kt * 16 + 2 * q + 1) * 32 + lane];
            const float* As = Ap + kt * 8;
            float a0 = As[0], a1 = As[8 * ST_F], a2 = As[4], a3 = As[4 + 8 * ST_F];
            mma8(acc[0], a0, a1, a2, a3, bb0.x, bb0.y);
            mma8(acc[1], a0, a1, a2, a3, bb1.x, bb1.y);
        }
        float* scr = arena + S_O;   // 4 x 128 partial scratch
        if (kh == 1 && r < 4) {
            #pragma unroll
            for (int j = 0; j < 2; j++) {
                int n0 = (2 * q + j) * 8 + 2 * c;
                scr[r * 128 + n0]     = acc[j][0];
                scr[r * 128 + n0 + 1] = acc[j][1];
            }
        }
        __syncthreads();
        if (kh == 0 && r < 4) {
            int t = t0 + r;
            #pragma unroll
            for (int j = 0; j < 2; j++) {
                int n0 = (2 * q + j) * 8 + 2 * c;
                float v0 = acc[j][0] + scr[r * 128 + n0]     + bf[n0];
                float v1 = acc[j][1] + scr[r * 128 + n0 + 1] + bf[n0 + 1];
                out[((long)b * 128 + n0) * 128 + t]     = v0;
                out[((long)b * 128 + n0 + 1) * 128 + t] = v1;
            }
        }
    }
}

extern "C" void kernel_launch(void* const* d_in, const int* in_sizes, int n_in,
                              void* d_out, int out_size) {
    (void)in_sizes; (void)n_in; (void)out_size;
    const float* p[30];
    for (int i = 0; i < 30; i++) p[i] = (const float*)d_in[i];

    static bool attr_set = false;
    if (!attr_set) {
        cudaFuncSetAttribute(encoder_kernel,
                             cudaFuncAttributeMaxDynamicSharedMemorySize,
                             ARENA_FLOATS * (int)sizeof(float));
        attr_set = true;
    }

    prep_weights<<<(FRAG_TOTAL + 255) / 256, 256>>>(
        p[2], p[3], p[4], p[5],          // b1 wq wk wv wo
        p[7], p[9],                      // b1 ff1 ff2
        p[15], p[16], p[17], p[18],      // b2 wq wk wv wo
        p[20], p[22],                    // b2 ff1 ff2
        p[28]);                          // wf

    encoder_kernel<<<2048, NT, ARENA_FLOATS * sizeof(float)>>>(
        p[0], p[1],
        p[6],  p[8],  p[10], p[11], p[12], p[13], p[14],   // b1 biases/LN
        p[19], p[21], p[23], p[24], p[25], p[26], p[27],   // b2 biases/LN
        p[29],
        (float*)d_out);
}

// round 6
// speedup vs baseline: 4.4899x; 1.0246x over previous
#include <cuda_runtime.h>

#define NT 512

// ---------------- fragment-linear tf32 weight scratch ----------------
// Permuted m16n8k8 B-fragment layout, kt-pairs packed for uint4 loads:
//   uint index = (nt*KTP + ktp)*128 + lane*4 + kk*2 + reg
//   kt = 2*ktp + kk ; k = kt*8 + 2*(lane&3) + reg ; n = nt*8 + (lane>>2)
// Matching A operand for logical (c, c+4) = physical cols (2c, 2c+1):
//   a0=X[r][2c], a1=X[r+8][2c], a2=X[r][2c+1], a3=X[r+8][2c+1]  -> float2 loads.
#define FRAG_TOTAL 686080
__device__ __align__(16) unsigned int g_wfrag[FRAG_TOTAL];

#define WFQ1 0
#define WFK1 26624
#define WFV1 53248
#define WFO1 79872
#define WF11 96256
#define WF21 161792
#define WFQ2 227328
#define WFK2 243712
#define WFV2 260096
#define WFO2 276480
#define WF12 292864
#define WF22 358400
#define WFWF 423936

__global__ void prep_weights(const float* __restrict__ q1, const float* __restrict__ k1,
                             const float* __restrict__ v1, const float* __restrict__ o1,
                             const float* __restrict__ f11, const float* __restrict__ f21,
                             const float* __restrict__ q2, const float* __restrict__ k2,
                             const float* __restrict__ v2, const float* __restrict__ o2,
                             const float* __restrict__ f12, const float* __restrict__ f22,
                             const float* __restrict__ wf) {
    int e = blockIdx.x * blockDim.x + threadIdx.x;
    if (e >= FRAG_TOTAL) return;
    const int offs[14] = {0,26624,53248,79872,96256,161792,227328,243712,260096,
                          276480,292864,358400,423936,686080};
    const int Kr[13] = {196,196,196,128,128,512,128,128,128,128,128,512,2048};
    const int Nn[13] = {128,128,128,128,512,128,128,128,128,128,512,128,128};
    int m = 0;
    while (e >= offs[m + 1]) m++;
    const float* W =
        m==0?q1: m==1?k1: m==2?v1: m==3?o1: m==4?f11: m==5?f21:
        m==6?q2: m==7?k2: m==8?v2: m==9?o2: m==10?f12: m==11?f22: wf;
    int l = e - offs[m];
    int N = Nn[m];
    int Kpad = (offs[m + 1] - offs[m]) / N;   // K rounded up to 16
    int KTP = Kpad >> 4;
    int blk = l >> 7, li = l & 127;
    int lane = li >> 2, kk = (li >> 1) & 1, reg = li & 1;
    int nt = blk / KTP, ktp = blk - nt * KTP;
    int kt = 2 * ktp + kk;
    int k = kt * 8 + 2 * (lane & 3) + reg;
    int n = nt * 8 + (lane >> 2);
    float v = (k < Kr[m]) ? W[k * N + n] : 0.f;
    unsigned int u;
    asm("cvt.rna.tf32.f32 %0, %1;" : "=r"(u) : "f"(v));
    g_wfrag[e] = u;
}

// ---------------- shared arena (floats) ----------------
// float2 A loads need stride/2 ≡ 4 or 12 (mod 16): 136, 216, 264, 2056 all OK.
#define ST_X   136
#define ST_XS  216
#define ST_FF  264
#define ST_F   2056
#define S_X2F  0        // 4 x 2056 real rows; frag rows 4..15 read later buffers (finite garbage, discarded)
#define S_O    8224     // 64 x 136
#define S_H    16928    // 64 x 136
#define S_X1   25632    // 64 x 136
#define S_FFH  34336    // 64 x 264 (xs 64 x 216 aliases here)
#define ARENA_FLOATS 51232

__device__ __forceinline__ void mma8(float* d, float a0, float a1, float a2, float a3,
                                     unsigned b0, unsigned b1) {
    asm volatile("mma.sync.aligned.m16n8k8.row.col.f32.tf32.tf32.f32 "
                 "{%0,%1,%2,%3}, {%4,%5,%6,%7}, {%8,%9}, {%0,%1,%2,%3};"
                 : "+f"(d[0]), "+f"(d[1]), "+f"(d[2]), "+f"(d[3])
                 : "r"(__float_as_uint(a0)), "r"(__float_as_uint(a1)),
                   "r"(__float_as_uint(a2)), "r"(__float_as_uint(a3)),
                   "r"(b0), "r"(b1));
}

__device__ __forceinline__ void warp_reduce2(float& s, float& s2) {
    #pragma unroll
    for (int off = 16; off; off >>= 1) {
        s  += __shfl_xor_sync(0xffffffffu, s,  off);
        s2 += __shfl_xor_sync(0xffffffffu, s2, off);
    }
}

// LayerNorm over 64 rows x 128 cols (stride ST_X buffers).
// If dstFlat: write (val [+dst_add]) to dstFlat[s*ST_F + w*128 + col].
__device__ void lnorm64(const float* __restrict__ src, const float* __restrict__ resid,
                        const float* __restrict__ g, const float* __restrict__ bta,
                        float* __restrict__ dst, const float* __restrict__ dst_add,
                        float* __restrict__ dstFlat) {
    int warp = threadIdx.x >> 5, lane = threadIdx.x & 31;
    #pragma unroll
    for (int rr = 0; rr < 4; rr++) {
        int row = warp + rr * 16;
        float v[4]; float s = 0.f, s2 = 0.f;
        #pragma unroll
        for (int i = 0; i < 4; i++) {
            int col = lane + 32 * i;
            float x = src[row * ST_X + col];
            if (resid) x += resid[row * ST_X + col];
            v[i] = x; s += x; s2 += x * x;
        }
        warp_reduce2(s, s2);
        float m   = s * (1.f / 128.f);
        float var = fmaxf(s2 * (1.f / 128.f) - m * m, 0.f);
        float inv = rsqrtf(var + 1e-5f);
        #pragma unroll
        for (int i = 0; i < 4; i++) {
            int col = lane + 32 * i;
            float val = (v[i] - m) * inv * g[col] + bta[col];
            if (dst_add) val += dst_add[row * ST_X + col];
            if (dstFlat) {
                int sq = row >> 4, w = row & 15;
                dstFlat[sq * ST_F + w * 128 + col] = val;
            } else {
                dst[row * ST_X + col] = val;
            }
        }
    }
}

// One transformer block over 4 sequences (64 rows). KTP = k-pair count of QKV.
template<int KTP, int SX>
__device__ void run_block(float* arena, const float* __restrict__ X,
                          const float* __restrict__ resid,
                          const uint4* __restrict__ Fq, const uint4* __restrict__ Fk,
                          const uint4* __restrict__ Fv, const uint4* __restrict__ Fo,
                          const uint4* __restrict__ F1, const uint4* __restrict__ F2,
                          const float* __restrict__ bo, const float* __restrict__ bf1,
                          const float* __restrict__ bf2,
                          const float* __restrict__ g1, const float* __restrict__ b1v,
                          const float* __restrict__ g2, const float* __restrict__ b2v,
                          float* __restrict__ dst, float* __restrict__ dstFlat) {
    const int warp = threadIdx.x >> 5, lane = threadIdx.x & 31;
    const int r = lane >> 2, c = lane & 3;
    float* o   = arena + S_O;
    float* h   = arena + S_H;
    float* ffh = arena + S_FFH;

    // ---- QKV (warp = nt, 4 seqs, q/k/v share A) + register attention ----
    {
        float aq[4][4] = {}, ak[4][4] = {}, av[4][4] = {};
        const float* Ap = X + r * SX + 2 * c;
        for (int ktp = 0; ktp < KTP; ktp++) {
            uint4 bq = Fq[(warp * KTP + ktp) * 32 + lane];
            uint4 bk = Fk[(warp * KTP + ktp) * 32 + lane];
            uint4 bv = Fv[(warp * KTP + ktp) * 32 + lane];
            #pragma unroll
            for (int s = 0; s < 4; s++) {
                const float* As = Ap + s * 16 * SX + ktp * 16;
                float2 lo0 = *(const float2*)(As);
                float2 hi0 = *(const float2*)(As + 8 * SX);
                float2 lo1 = *(const float2*)(As + 8);
                float2 hi1 = *(const float2*)(As + 8 * SX + 8);
                mma8(aq[s], lo0.x, hi0.x, lo0.y, hi0.y, bq.x, bq.y);
                mma8(ak[s], lo0.x, hi0.x, lo0.y, hi0.y, bk.x, bk.y);
                mma8(av[s], lo0.x, hi0.x, lo0.y, hi0.y, bv.x, bv.y);
                mma8(aq[s], lo1.x, hi1.x, lo1.y, hi1.y, bq.z, bq.w);
                mma8(ak[s], lo1.x, hi1.x, lo1.y, hi1.y, bk.z, bk.w);
                mma8(av[s], lo1.x, hi1.x, lo1.y, hi1.y, bv.z, bv.w);
            }
        }
        // attention: thread owns head hh = warp*4 + c, q rows r and r+8, seq s
        const float scale = 0.70710678118654752f;
        #pragma unroll
        for (int s = 0; s < 4; s++) {
            float sumA = 0.f, sumB = 0.f;
            float oA0 = 0.f, oA1 = 0.f, oB0 = 0.f, oB1 = 0.f;
            #pragma unroll
            for (int rp = 0; rp < 8; rp++) {
                int src = rp * 4 + c;
                float k00 = __shfl_sync(0xffffffffu, ak[s][0], src);
                float k01 = __shfl_sync(0xffffffffu, ak[s][1], src);
                float k10 = __shfl_sync(0xffffffffu, ak[s][2], src);
                float k11 = __shfl_sync(0xffffffffu, ak[s][3], src);
                float v00 = __shfl_sync(0xffffffffu, av[s][0], src);
                float v01 = __shfl_sync(0xffffffffu, av[s][1], src);
                float v10 = __shfl_sync(0xffffffffu, av[s][2], src);
                float v11 = __shfl_sync(0xffffffffu, av[s][3], src);
                float eA0 = __expf((aq[s][0] * k00 + aq[s][1] * k01) * scale);
                float eA1 = __expf((aq[s][0] * k10 + aq[s][1] * k11) * scale);
                float eB0 = __expf((aq[s][2] * k00 + aq[s][3] * k01) * scale);
                float eB1 = __expf((aq[s][2] * k10 + aq[s][3] * k11) * scale);
                sumA += eA0 + eA1; sumB += eB0 + eB1;
                oA0 += eA0 * v00 + eA1 * v10; oA1 += eA0 * v01 + eA1 * v11;
                oB0 += eB0 * v00 + eB1 * v10; oB1 += eB0 * v01 + eB1 * v11;
            }
            int n0 = warp * 8 + 2 * c;
            float iA = 1.f / sumA, iB = 1.f / sumB;
            *(float2*)(o + (s * 16 + r) * ST_X + n0)     = make_float2(oA0 * iA, oA1 * iA);
            *(float2*)(o + (s * 16 + r + 8) * ST_X + n0) = make_float2(oB0 * iB, oB1 * iB);
        }
    }
    __syncthreads();

    const int sp = warp >> 3, q = warp & 7;   // 2-seq group, nt group

    // ---- WO: warp = (2 nt, 2 seq), KTP=8 ----
    {
        float acc[2][2][4] = {};
        const float* Ap = o + (sp * 32 + r) * ST_X + 2 * c;
        for (int ktp = 0; ktp < 8; ktp++) {
            uint4 bb0 = Fo[((2 * q)     * 8 + ktp) * 32 + lane];
            uint4 bb1 = Fo[((2 * q + 1) * 8 + ktp) * 32 + lane];
            #pragma unroll
            for (int s = 0; s < 2; s++) {
                const float* As = Ap + s * 16 * ST_X + ktp * 16;
                float2 lo0 = *(const float2*)(As);
                float2 hi0 = *(const float2*)(As + 8 * ST_X);
                float2 lo1 = *(const float2*)(As + 8);
                float2 hi1 = *(const float2*)(As + 8 * ST_X + 8);
                mma8(acc[0][s], lo0.x, hi0.x, lo0.y, hi0.y, bb0.x, bb0.y);
                mma8(acc[1][s], lo0.x, hi0.x, lo0.y, hi0.y, bb1.x, bb1.y);
                mma8(acc[0][s], lo1.x, hi1.x, lo1.y, hi1.y, bb0.z, bb0.w);
                mma8(acc[1][s], lo1.x, hi1.x, lo1.y, hi1.y, bb1.z, bb1.w);
            }
        }
        #pragma unroll
        for (int j = 0; j < 2; j++) {
            int n0 = (2 * q + j) * 8 + 2 * c;
            float2 bb = *(const float2*)(bo + n0);
            #pragma unroll
            for (int s = 0; s < 2; s++) {
                int row = (sp * 2 + s) * 16 + r;
                *(float2*)(h + row * ST_X + n0)       = make_float2(acc[j][s][0] + bb.x, acc[j][s][1] + bb.y);
                *(float2*)(h + (row + 8) * ST_X + n0) = make_float2(acc[j][s][2] + bb.x, acc[j][s][3] + bb.y);
            }
        }
    }
    __syncthreads();

    lnorm64(h, resid, g1, b1v, h, nullptr, nullptr);
    __syncthreads();

    // ---- FF in two N=256 halves; FF2 accumulates across halves ----
    float accF2[2][2][4] = {};
    #pragma unroll
    for (int half = 0; half < 2; half++) {
        // FF1: warp = (4 nt local, 2 seq), KTP=8; B nt index global (0..63)
        {
            float a1a[4][2][4] = {};
            const float* Ap = h + (sp * 32 + r) * ST_X + 2 * c;
            for (int ktp = 0; ktp < 8; ktp++) {
                uint4 bb[4];
                #pragma unroll
                for (int j = 0; j < 4; j++)
                    bb[j] = F1[((half * 32 + q * 4 + j) * 8 + ktp) * 32 + lane];
                #pragma unroll
                for (int s = 0; s < 2; s++) {
                    const float* As = Ap + s * 16 * ST_X + ktp * 16;
                    float2 lo0 = *(const float2*)(As);
                    float2 hi0 = *(const float2*)(As + 8 * ST_X);
                    float2 lo1 = *(const float2*)(As + 8);
                    float2 hi1 = *(const float2*)(As + 8 * ST_X + 8);
                    #pragma unroll
                    for (int j = 0; j < 4; j++) {
                        mma8(a1a[j][s], lo0.x, hi0.x, lo0.y, hi0.y, bb[j].x, bb[j].y);
                        mma8(a1a[j][s], lo1.x, hi1.x, lo1.y, hi1.y, bb[j].z, bb[j].w);
                    }
                }
            }
            #pragma unroll
            for (int j = 0; j < 4; j++) {
                int n0l = (q * 4 + j) * 8 + 2 * c;
                float2 bb = *(const float2*)(bf1 + half * 256 + n0l);
                #pragma unroll
                for (int s = 0; s < 2; s++) {
                    int row = (sp * 2 + s) * 16 + r;
                    *(float2*)(ffh + row * ST_FF + n0l) =
                        make_float2(fmaxf(a1a[j][s][0] + bb.x, 0.f), fmaxf(a1a[j][s][1] + bb.y, 0.f));
                    *(float2*)(ffh + (row + 8) * ST_FF + n0l) =
                        make_float2(fmaxf(a1a[j][s][2] + bb.x, 0.f), fmaxf(a1a[j][s][3] + bb.y, 0.f));
                }
            }
        }
        __syncthreads();
        // FF2: warp = (2 nt, 2 seq); local KTP=16, global B KTP=32
        {
            const float* Ap = ffh + (sp * 32 + r) * ST_FF + 2 * c;
            for (int ktp = 0; ktp < 16; ktp++) {
                uint4 bb0 = F2[((2 * q)     * 32 + half * 16 + ktp) * 32 + lane];
                uint4 bb1 = F2[((2 * q + 1) * 32 + half * 16 + ktp) * 32 + lane];
                #pragma unroll
                for (int s = 0; s < 2; s++) {
                    const float* As = Ap + s * 16 * ST_FF + ktp * 16;
                    float2 lo0 = *(const float2*)(As);
                    float2 hi0 = *(const float2*)(As + 8 * ST_FF);
                    float2 lo1 = *(const float2*)(As + 8);
                    float2 hi1 = *(const float2*)(As + 8 * ST_FF + 8);
                    mma8(accF2[0][s], lo0.x, hi0.x, lo0.y, hi0.y, bb0.x, bb0.y);
                    mma8(accF2[1][s], lo0.x, hi0.x, lo0.y, hi0.y, bb1.x, bb1.y);
                    mma8(accF2[0][s], lo1.x, hi1.x, lo1.y, hi1.y, bb0.z, bb0.w);
                    mma8(accF2[1][s], lo1.x, hi1.x, lo1.y, hi1.y, bb1.z, bb1.w);
                }
            }
        }
        __syncthreads();
    }
    // write FF2 result to o
    #pragma unroll
    for (int j = 0; j < 2; j++) {
        int n0 = (2 * q + j) * 8 + 2 * c;
        float2 bb = *(const float2*)(bf2 + n0);
        #pragma unroll
        for (int s = 0; s < 2; s++) {
            int row = (sp * 2 + s) * 16 + r;
            *(float2*)(o + row * ST_X + n0)       = make_float2(accF2[j][s][0] + bb.x, accF2[j][s][1] + bb.y);
            *(float2*)(o + (row + 8) * ST_X + n0) = make_float2(accF2[j][s][2] + bb.x, accF2[j][s][3] + bb.y);
        }
    }
    __syncthreads();

    lnorm64(o, h, g2, b2v, dst, resid, dstFlat);
    __syncthreads();
}

__global__ void __launch_bounds__(NT, 1)
encoder_kernel(const float* __restrict__ enc, const float* __restrict__ off,
               const float* __restrict__ b1_bo, const float* __restrict__ b1_bf1,
               const float* __restrict__ b1_bf2,
               const float* __restrict__ b1_g1, const float* __restrict__ b1_b1,
               const float* __restrict__ b1_g2, const float* __restrict__ b1_b2,
               const float* __restrict__ b2_bo, const float* __restrict__ b2_bf1,
               const float* __restrict__ b2_bf2,
               const float* __restrict__ b2_g1, const float* __restrict__ b2_b1,
               const float* __restrict__ b2_g2, const float* __restrict__ b2_b2,
               const float* __restrict__ bf, float* __restrict__ out) {
    extern __shared__ float arena[];
    const int tid = threadIdx.x;
    const int warp = tid >> 5, lane = tid & 31;
    const int r = lane >> 2, c = lane & 3;
    const int b = blockIdx.x >> 5;
    const int t0 = (blockIdx.x & 31) << 2;

    float* x2f = arena + S_X2F;
    float* x1  = arena + S_X1;
    float* xs  = arena + S_FFH;   // aliases ffh (dead until FF1)

    // ---- windowed input: 4 seqs x 16 x 208 (stride 216), cols 196..207 zero ----
    for (int i = tid; i < 64 * 208; i += NT) {
        int row = i / 208, cc = i - row * 208;
        int s = row >> 4, w = row & 15;
        int tc = min(max(t0 + s + w - 8, 0), 127);
        float val = 0.f;
        if (cc < 112)      val = enc[((long)b * 112 + cc) * 128 + tc];
        else if (cc < 196) val = off[b * 84 + (cc - 112)];
        xs[row * ST_XS + cc] = val;
    }
    __syncthreads();

    const unsigned* G = g_wfrag;
    // block 1: CIN=196(pad208) -> 128, no residual; dst = x1. KTP=13.
    run_block<13, ST_XS>(arena, xs, nullptr,
                         (const uint4*)(G + WFQ1), (const uint4*)(G + WFK1),
                         (const uint4*)(G + WFV1), (const uint4*)(G + WFO1),
                         (const uint4*)(G + WF11), (const uint4*)(G + WF21),
                         b1_bo, b1_bf1, b1_bf2, b1_g1, b1_b1, b1_g2, b1_b2,
                         x1, nullptr);

    // block 2: 128 -> 128 with residual; x2 = x1 + blk(x1) written FLAT. KTP=8.
    run_block<8, ST_X>(arena, x1, x1,
                       (const uint4*)(G + WFQ2), (const uint4*)(G + WFK2),
                       (const uint4*)(G + WFV2), (const uint4*)(G + WFO2),
                       (const uint4*)(G + WF12), (const uint4*)(G + WF22),
                       b2_bo, b2_bf1, b2_bf2, b2_g1, b2_b1, b2_g2, b2_b2,
                       nullptr, x2f);

    // ---- final projection as MMA: C(16x128) = x2f(16x2048) @ wf ----
    {
        const uint4* Fw = (const uint4*)(G + WFWF);
        const int kh = warp >> 3, q = warp & 7;
        float acc[2][4] = {};
        const float* Ap = x2f + r * ST_F + 2 * c;
        for (int ktp = 0; ktp < 64; ktp++) {
            int ktg = kh * 64 + ktp;
            uint4 bb0 = Fw[((2 * q)     * 128 + ktg) * 32 + lane];
            uint4 bb1 = Fw[((2 * q + 1) * 128 + ktg) * 32 + lane];
            const float* As = Ap + ktg * 16;
            float2 lo0 = *(const float2*)(As);
            float2 hi0 = *(const float2*)(As + 8 * ST_F);
            float2 lo1 = *(const float2*)(As + 8);
            float2 hi1 = *(const float2*)(As + 8 * ST_F + 8);
            mma8(acc[0], lo0.x, hi0.x, lo0.y, hi0.y, bb0.x, bb0.y);
            mma8(acc[1], lo0.x, hi0.x, lo0.y, hi0.y, bb1.x, bb1.y);
            mma8(acc[0], lo1.x, hi1.x, lo1.y, hi1.y, bb0.z, bb0.w);
            mma8(acc[1], lo1.x, hi1.x, lo1.y, hi1.y, bb1.z, bb1.w);
        }
        float* scr = arena + S_O;   // 4 x 128 partial scratch
        if (kh == 1 && r < 4) {
            #pragma unroll
            for (int j = 0; j < 2; j++) {
                int n0 = (2 * q + j) * 8 + 2 * c;
                scr[r * 128 + n0]     = acc[j][0];
                scr[r * 128 + n0 + 1] = acc[j][1];
            }
        }
        __syncthreads();
        if (kh == 0 && r < 4) {
            int t = t0 + r;
            #pragma unroll
            for (int j = 0; j < 2; j++) {
                int n0 = (2 * q + j) * 8 + 2 * c;
                float v0 = acc[j][0] + scr[r * 128 + n0]     + bf[n0];
                float v1 = acc[j][1] + scr[r * 128 + n0 + 1] + bf[n0 + 1];
                out[((long)b * 128 + n0) * 128 + t]     = v0;
                out[((long)b * 128 + n0 + 1) * 128 + t] = v1;
            }
        }
    }
}

extern "C" void kernel_launch(void* const* d_in, const int* in_sizes, int n_in,
                              void* d_out, int out_size) {
    (void)in_sizes; (void)n_in; (void)out_size;
    const float* p[30];
    for (int i = 0; i < 30; i++) p[i] = (const float*)d_in[i];

    static bool attr_set = false;
    if (!attr_set) {
        cudaFuncSetAttribute(encoder_kernel,
                             cudaFuncAttributeMaxDynamicSharedMemorySize,
                             ARENA_FLOATS * (int)sizeof(float));
        attr_set = true;
    }

    prep_weights<<<(FRAG_TOTAL + 255) / 256, 256>>>(
        p[2], p[3], p[4], p[5],          // b1 wq wk wv wo
        p[7], p[9],                      // b1 ff1 ff2
        p[15], p[16], p[17], p[18],      // b2 wq wk wv wo
        p[20], p[22],                    // b2 ff1 ff2
        p[28]);                          // wf

    encoder_kernel<<<2048, NT, ARENA_FLOATS * sizeof(float)>>>(
        p[0], p[1],
        p[6],  p[8],  p[10], p[11], p[12], p[13], p[14],   // b1 biases/LN
        p[19], p[21], p[23], p[24], p[25], p[26], p[27],   // b2 biases/LN
        p[29],
        (float*)d_out);
}

// round 8
// speedup vs baseline: 6.5847x; 1.4666x over previous
#include <cuda_runtime.h>
#include <cuda_fp16.h>

#define NT 512

// ---------------- fp16 fragment-linear weight scratch ----------------
// m16n8k16 f16 B-fragments, k32 (2 k16 tiles) packed per uint4:
//   uint index = (nt*KTP + ktp)*128 + lane*4 + kk*2 + reg   (each uint = half2)
//   k16 tile kt = 2*ktp + kk; half2 = W[kbase][n], W[kbase+1][n]
//   kbase = kt*16 + reg*8 + 2*(lane&3) ; n = nt*8 + (lane>>2)
#define FRAG_TOTAL 346112
__device__ __align__(16) unsigned int g_wfrag[FRAG_TOTAL];

#define WFQ1 0
#define WFK1 14336
#define WFV1 28672
#define WFO1 43008
#define WF11 51200
#define WF21 83968
#define WFQ2 116736
#define WFK2 124928
#define WFV2 133120
#define WFO2 141312
#define WF12 149504
#define WF22 182272
#define WFWF 215040

__global__ void prep_weights(const float* __restrict__ q1, const float* __restrict__ k1,
                             const float* __restrict__ v1, const float* __restrict__ o1,
                             const float* __restrict__ f11, const float* __restrict__ f21,
                             const float* __restrict__ q2, const float* __restrict__ k2,
                             const float* __restrict__ v2, const float* __restrict__ o2,
                             const float* __restrict__ f12, const float* __restrict__ f22,
                             const float* __restrict__ wf) {
    int e = blockIdx.x * blockDim.x + threadIdx.x;
    if (e >= FRAG_TOTAL) return;
    const int offs[14] = {0,14336,28672,43008,51200,83968,116736,124928,133120,
                          141312,149504,182272,215040,346112};
    const int Kr[13] = {196,196,196,128,128,512,128,128,128,128,128,512,2048};
    const int Nn[13] = {128,128,128,128,512,128,128,128,128,128,512,128,128};
    int m = 0;
    while (e >= offs[m + 1]) m++;
    const float* W =
        m==0?q1: m==1?k1: m==2?v1: m==3?o1: m==4?f11: m==5?f21:
        m==6?q2: m==7?k2: m==8?v2: m==9?o2: m==10?f12: m==11?f22: wf;
    int l = e - offs[m];
    int N = Nn[m], K = Kr[m];
    int KTPm = (offs[m + 1] - offs[m]) / (16 * N);   // k32 steps
    int blk = l >> 7, li = l & 127;
    int lane = li >> 2, kk = (li >> 1) & 1, reg = li & 1;
    int nt = blk / KTPm, ktp = blk - nt * KTPm;
    int kbase = (2 * ktp + kk) * 16 + reg * 8 + 2 * (lane & 3);
    int n = nt * 8 + (lane >> 2);
    float wa = (kbase     < K) ? W[(long)kbase * N + n] : 0.f;
    float wb = (kbase + 1 < K) ? W[(long)(kbase + 1) * N + n] : 0.f;
    __half2 h2 = __floats2half2_rn(wa, wb);
    g_wfrag[e] = *reinterpret_cast<unsigned int*>(&h2);
}

// ---------------- shared arena ----------------
// fp32 buffers (stride 136) for LN/residual precision; fp16 mirrors feed GEMM A.
// half strides: bytes/8 mod 16 ∈ {4,12}: 144(288B),240(480B),272(544B),2064(4128B)
#define ST_X    136
#define STH_X   144
#define STH_XS  240
#define STH_FF  272
#define STH_F   2064
#define S_O     0
#define S_H     8704
#define S_X1    17408
#define S_HALF  26112          // half region starts here (float offset)
#define H_OH    0              // 64 x 144
#define H_HH    9216           // 64 x 144
#define H_X1H   18432          // 64 x 144
#define H_FFH   27648          // 64 x 272 (xs 64 x 240 aliases here)
#define H_X2F   45056          // 4 x 2064
#define ARENA_FLOATS 52768

// logical col (0..15) within a k16 group -> physical position
__device__ __forceinline__ int permc(int l) {
    return (l < 8) ? ((l >> 1) * 4 + (l & 1)) : (((l - 8) >> 1) * 4 + 2 + (l & 1));
}
__device__ __forceinline__ int pcol(int col) {   // full permuted column
    return (col >> 4) * 16 + permc(col & 15);
}

__device__ __forceinline__ void mma16(float* d, unsigned a0, unsigned a1,
                                      unsigned a2, unsigned a3,
                                      unsigned b0, unsigned b1) {
    asm volatile("mma.sync.aligned.m16n8k16.row.col.f32.f16.f16.f32 "
                 "{%0,%1,%2,%3}, {%4,%5,%6,%7}, {%8,%9}, {%0,%1,%2,%3};"
                 : "+f"(d[0]), "+f"(d[1]), "+f"(d[2]), "+f"(d[3])
                 : "r"(a0), "r"(a1), "r"(a2), "r"(a3), "r"(b0), "r"(b1));
}

__device__ __forceinline__ void warp_reduce2(float& s, float& s2) {
    #pragma unroll
    for (int off = 16; off; off >>= 1) {
        s  += __shfl_xor_sync(0xffffffffu, s,  off);
        s2 += __shfl_xor_sync(0xffffffffu, s2, off);
    }
}

// LayerNorm over 64 rows x 128 cols.
// dstF (fp32, stride ST_X) optional; dstH (fp16, permuted) optional:
//   flat=0: pos = row*STH_X + pcol(col);  flat=1: pos = (row>>4)*STH_F + pcol((row&15)*128+col)
__device__ void lnorm64(const float* __restrict__ src, const float* __restrict__ resid,
                        const float* __restrict__ g, const float* __restrict__ bta,
                        const float* __restrict__ dst_add,
                        float* __restrict__ dstF, __half* __restrict__ dstH, int flat) {
    int warp = threadIdx.x >> 5, lane = threadIdx.x & 31;
    #pragma unroll
    for (int rr = 0; rr < 4; rr++) {
        int row = warp + rr * 16;
        float v[4]; float s = 0.f, s2 = 0.f;
        #pragma unroll
        for (int i = 0; i < 4; i++) {
            int col = lane + 32 * i;
            float x = src[row * ST_X + col];
            if (resid) x += resid[row * ST_X + col];
            v[i] = x; s += x; s2 += x * x;
        }
        warp_reduce2(s, s2);
        float m   = s * (1.f / 128.f);
        float var = fmaxf(s2 * (1.f / 128.f) - m * m, 0.f);
        float inv = rsqrtf(var + 1e-5f);
        #pragma unroll
        for (int i = 0; i < 4; i++) {
            int col = lane + 32 * i;
            float val = (v[i] - m) * inv * g[col] + bta[col];
            if (dst_add) val += dst_add[row * ST_X + col];
            if (dstF) dstF[row * ST_X + col] = val;
            if (dstH) {
                int pos = flat ? (row >> 4) * STH_F + pcol((row & 15) * 128 + col)
                               : row * STH_X + pcol(col);
                dstH[pos] = __float2half_rn(val);
            }
        }
    }
}

// One transformer block over 4 sequences. Xh: fp16 A input (stride SXH), KTP = k32 steps.
template<int KTP, int SXH>
__device__ void run_block(float* arena, const __half* __restrict__ Xh,
                          const float* __restrict__ resid,
                          const uint4* __restrict__ Fq, const uint4* __restrict__ Fk,
                          const uint4* __restrict__ Fv, const uint4* __restrict__ Fo,
                          const uint4* __restrict__ F1, const uint4* __restrict__ F2,
                          const float* __restrict__ bo, const float* __restrict__ bf1,
                          const float* __restrict__ bf2,
                          const float* __restrict__ g1, const float* __restrict__ b1v,
                          const float* __restrict__ g2, const float* __restrict__ b2v,
                          float* __restrict__ dstF, __half* __restrict__ dstH, int flat) {
    const int warp = threadIdx.x >> 5, lane = threadIdx.x & 31;
    const int r = lane >> 2, c = lane & 3;
    float*  o   = arena + S_O;
    float*  h   = arena + S_H;
    __half* hb  = (__half*)(arena + S_HALF);
    __half* oh  = hb + H_OH;
    __half* hh  = hb + H_HH;
    __half* ffh = hb + H_FFH;

    // ---- QKV (warp = nt, 4 seqs) + register attention ----
    {
        float aq[4][4] = {}, ak[4][4] = {}, av[4][4] = {};
        const __half* Ah = Xh + r * SXH + 4 * c;
        for (int ktp = 0; ktp < KTP; ktp++) {
            uint4 bq = Fq[(warp * KTP + ktp) * 32 + lane];
            uint4 bk = Fk[(warp * KTP + ktp) * 32 + lane];
            uint4 bv = Fv[(warp * KTP + ktp) * 32 + lane];
            #pragma unroll
            for (int s = 0; s < 4; s++) {
                const __half* As = Ah + s * 16 * SXH;
                #pragma unroll
                for (int kk = 0; kk < 2; kk++) {
                    int g = (ktp * 2 + kk) * 16;
                    uint2 lo = *(const uint2*)(As + g);
                    uint2 hi = *(const uint2*)(As + 8 * SXH + g);
                    mma16(aq[s], lo.x, hi.x, lo.y, hi.y, kk ? bq.z : bq.x, kk ? bq.w : bq.y);
                    mma16(ak[s], lo.x, hi.x, lo.y, hi.y, kk ? bk.z : bk.x, kk ? bk.w : bk.y);
                    mma16(av[s], lo.x, hi.x, lo.y, hi.y, kk ? bv.z : bv.x, kk ? bv.w : bv.y);
                }
            }
        }
        const float scale = 0.70710678118654752f;
        int gpos = (warp >> 1) * 16 + 4 * c + 2 * (warp & 1);
        #pragma unroll
        for (int s = 0; s < 4; s++) {
            float sumA = 0.f, sumB = 0.f;
            float oA0 = 0.f, oA1 = 0.f, oB0 = 0.f, oB1 = 0.f;
            #pragma unroll
            for (int rp = 0; rp < 8; rp++) {
                int src = rp * 4 + c;
                float k00 = __shfl_sync(0xffffffffu, ak[s][0], src);
                float k01 = __shfl_sync(0xffffffffu, ak[s][1], src);
                float k10 = __shfl_sync(0xffffffffu, ak[s][2], src);
                float k11 = __shfl_sync(0xffffffffu, ak[s][3], src);
                float v00 = __shfl_sync(0xffffffffu, av[s][0], src);
                float v01 = __shfl_sync(0xffffffffu, av[s][1], src);
                float v10 = __shfl_sync(0xffffffffu, av[s][2], src);
                float v11 = __shfl_sync(0xffffffffu, av[s][3], src);
                float eA0 = __expf((aq[s][0] * k00 + aq[s][1] * k01) * scale);
                float eA1 = __expf((aq[s][0] * k10 + aq[s][1] * k11) * scale);
                float eB0 = __expf((aq[s][2] * k00 + aq[s][3] * k01) * scale);
                float eB1 = __expf((aq[s][2] * k10 + aq[s][3] * k11) * scale);
                sumA += eA0 + eA1; sumB += eB0 + eB1;
                oA0 += eA0 * v00 + eA1 * v10; oA1 += eA0 * v01 + eA1 * v11;
                oB0 += eB0 * v00 + eB1 * v10; oB1 += eB0 * v01 + eB1 * v11;
            }
            float iA = 1.f / sumA, iB = 1.f / sumB;
            *(__half2*)(oh + (s * 16 + r) * STH_X + gpos)     = __floats2half2_rn(oA0 * iA, oA1 * iA);
            *(__half2*)(oh + (s * 16 + r + 8) * STH_X + gpos) = __floats2half2_rn(oB0 * iB, oB1 * iB);
        }
    }
    __syncthreads();

    const int sp = warp >> 3, q = warp & 7;

    // ---- WO: warp = (2 nt, 2 seq), KTP=4 ----
    {
        float acc[2][2][4] = {};
        const __half* Ah = oh + (sp * 32 + r) * STH_X + 4 * c;
        for (int ktp = 0; ktp < 4; ktp++) {
            uint4 bb0 = Fo[((2 * q)     * 4 + ktp) * 32 + lane];
            uint4 bb1 = Fo[((2 * q + 1) * 4 + ktp) * 32 + lane];
            #pragma unroll
            for (int s = 0; s < 2; s++) {
                const __half* As = Ah + s * 16 * STH_X;
                #pragma unroll
                for (int kk = 0; kk < 2; kk++) {
                    int g = (ktp * 2 + kk) * 16;
                    uint2 lo = *(const uint2*)(As + g);
                    uint2 hi = *(const uint2*)(As + 8 * STH_X + g);
                    mma16(acc[0][s], lo.x, hi.x, lo.y, hi.y, kk ? bb0.z : bb0.x, kk ? bb0.w : bb0.y);
                    mma16(acc[1][s], lo.x, hi.x, lo.y, hi.y, kk ? bb1.z : bb1.x, kk ? bb1.w : bb1.y);
                }
            }
        }
        #pragma unroll
        for (int j = 0; j < 2; j++) {
            int n0 = (2 * q + j) * 8 + 2 * c;
            float2 bb = *(const float2*)(bo + n0);
            #pragma unroll
            for (int s = 0; s < 2; s++) {
                int row = (sp * 2 + s) * 16 + r;
                *(float2*)(h + row * ST_X + n0)       = make_float2(acc[j][s][0] + bb.x, acc[j][s][1] + bb.y);
                *(float2*)(h + (row + 8) * ST_X + n0) = make_float2(acc[j][s][2] + bb.x, acc[j][s][3] + bb.y);
            }
        }
    }
    __syncthreads();

    // LN1: h <- LN(h [+resid]) fp32 in place, fp16 mirror hh
    lnorm64(h, resid, g1, b1v, nullptr, h, hh, 0);
    __syncthreads();

    // ---- FF in two N=256 halves ----
    float accF2[2][2][4] = {};
    #pragma unroll
    for (int half = 0; half < 2; half++) {
        {   // FF1: warp = (4 nt local, 2 seq), KTP=4
            float a1a[4][2][4] = {};
            const __half* Ah = hh + (sp * 32 + r) * STH_X + 4 * c;
            for (int ktp = 0; ktp < 4; ktp++) {
                uint4 bb[4];
                #pragma unroll
                for (int j = 0; j < 4; j++)
                    bb[j] = F1[((half * 32 + q * 4 + j) * 4 + ktp) * 32 + lane];
                #pragma unroll
                for (int s = 0; s < 2; s++) {
                    const __half* As = Ah + s * 16 * STH_X;
                    #pragma unroll
                    for (int kk = 0; kk < 2; kk++) {
                        int g = (ktp * 2 + kk) * 16;
                        uint2 lo = *(const uint2*)(As + g);
                        uint2 hi = *(const uint2*)(As + 8 * STH_X + g);
                        #pragma unroll
                        for (int j = 0; j < 4; j++)
                            mma16(a1a[j][s], lo.x, hi.x, lo.y, hi.y,
                                  kk ? bb[j].z : bb[j].x, kk ? bb[j].w : bb[j].y);
                    }
                }
            }
            #pragma unroll
            for (int j = 0; j < 4; j++) {
                int ntl = q * 4 + j;
                int gpos = (ntl >> 1) * 16 + 4 * c + 2 * (ntl & 1);
                float2 bb = *(const float2*)(bf1 + half * 256 + ntl * 8 + 2 * c);
                #pragma unroll
                for (int s = 0; s < 2; s++) {
                    int row = (sp * 2 + s) * 16 + r;
                    *(__half2*)(ffh + row * STH_FF + gpos) =
                        __floats2half2_rn(fmaxf(a1a[j][s][0] + bb.x, 0.f), fmaxf(a1a[j][s][1] + bb.y, 0.f));
                    *(__half2*)(ffh + (row + 8) * STH_FF + gpos) =
                        __floats2half2_rn(fmaxf(a1a[j][s][2] + bb.x, 0.f), fmaxf(a1a[j][s][3] + bb.y, 0.f));
                }
            }
        }
        __syncthreads();
        {   // FF2: warp = (2 nt, 2 seq); local KTP=8, global 16
            const __half* Ah = ffh + (sp * 32 + r) * STH_FF + 4 * c;
            for (int ktp = 0; ktp < 8; ktp++) {
                uint4 bb0 = F2[((2 * q)     * 16 + half * 8 + ktp) * 32 + lane];
                uint4 bb1 = F2[((2 * q + 1) * 16 + half * 8 + ktp) * 32 + lane];
                #pragma unroll
                for (int s = 0; s < 2; s++) {
                    const __half* As = Ah + s * 16 * STH_FF;
                    #pragma unroll
                    for (int kk = 0; kk < 2; kk++) {
                        int g = (ktp * 2 + kk) * 16;
                        uint2 lo = *(const uint2*)(As + g);
                        uint2 hi = *(const uint2*)(As + 8 * STH_FF + g);
                        mma16(accF2[0][s], lo.x, hi.x, lo.y, hi.y, kk ? bb0.z : bb0.x, kk ? bb0.w : bb0.y);
                        mma16(accF2[1][s], lo.x, hi.x, lo.y, hi.y, kk ? bb1.z : bb1.x, kk ? bb1.w : bb1.y);
                    }
                }
            }
        }
        __syncthreads();
    }
    #pragma unroll
    for (int j = 0; j < 2; j++) {
        int n0 = (2 * q + j) * 8 + 2 * c;
        float2 bb = *(const float2*)(bf2 + n0);
        #pragma unroll
        for (int s = 0; s < 2; s++) {
            int row = (sp * 2 + s) * 16 + r;
            *(float2*)(o + row * ST_X + n0)       = make_float2(accF2[j][s][0] + bb.x, accF2[j][s][1] + bb.y);
            *(float2*)(o + (row + 8) * ST_X + n0) = make_float2(accF2[j][s][2] + bb.x, accF2[j][s][3] + bb.y);
        }
    }
    __syncthreads();

    lnorm64(o, h, g2, b2v, resid /* dst_add: x1 for block2, null for block1 */,
            dstF, dstH, flat);
    __syncthreads();
}

__global__ void __launch_bounds__(NT, 1)
encoder_kernel(const float* __restrict__ enc, const float* __restrict__ off,
               const float* __restrict__ b1_bo, const float* __restrict__ b1_bf1,
               const float* __restrict__ b1_bf2,
               const float* __restrict__ b1_g1, const float* __restrict__ b1_b1,
               const float* __restrict__ b1_g2, const float* __restrict__ b1_b2,
               const float* __restrict__ b2_bo, const float* __restrict__ b2_bf1,
               const float* __restrict__ b2_bf2,
               const float* __restrict__ b2_g1, const float* __restrict__ b2_b1,
               const float* __restrict__ b2_g2, const float* __restrict__ b2_b2,
               const float* __restrict__ bf, float* __restrict__ out) {
    extern __shared__ float arena[];
    const int tid = threadIdx.x;
    const int warp = tid >> 5, lane = tid & 31;
    const int r = lane >> 2, c = lane & 3;
    const int b = blockIdx.x >> 5;
    const int t0 = (blockIdx.x & 31) << 2;

    __half* hb   = (__half*)(arena + S_HALF);
    __half* xs   = hb + H_FFH;    // aliases ffh (dead until FF1)
    __half* x1h  = hb + H_X1H;
    __half* x2fh = hb + H_X2F;
    float*  x1   = arena + S_X1;

    // ---- windowed input: 4 seqs x 16 x 224 (stride 240, permuted cols), 196.. zero ----
    for (int i = tid; i < 64 * 224; i += NT) {
        int row = i / 224, cc = i - row * 224;
        int s = row >> 4, w = row & 15;
        int tc = min(max(t0 + s + w - 8, 0), 127);
        float val = 0.f;
        if (cc < 112)      val = enc[((long)b * 112 + cc) * 128 + tc];
        else if (cc < 196) val = off[b * 84 + (cc - 112)];
        xs[row * STH_XS + pcol(cc)] = __float2half_rn(val);
    }
    __syncthreads();

    const unsigned* G = g_wfrag;
    // block 1: K=196(pad224) -> 128, no residual; out: x1 fp32 + x1h mirror. KTP=7.
    run_block<7, STH_XS>(arena, xs, nullptr,
                         (const uint4*)(G + WFQ1), (const uint4*)(G + WFK1),
                         (const uint4*)(G + WFV1), (const uint4*)(G + WFO1),
                         (const uint4*)(G + WF11), (const uint4*)(G + WF21),
                         b1_bo, b1_bf1, b1_bf2, b1_g1, b1_b1, b1_g2, b1_b2,
                         x1, x1h, 0);

    // block 2: 128 -> 128 with residual; x2 = x1 + blk(x1) written FLAT fp16. KTP=4.
    run_block<4, STH_X>(arena, x1h, x1,
                        (const uint4*)(G + WFQ2), (const uint4*)(G + WFK2),
                        (const uint4*)(G + WFV2), (const uint4*)(G + WFO2),
                        (const uint4*)(G + WF12), (const uint4*)(G + WF22),
                        b2_bo, b2_bf1, b2_bf2, b2_g1, b2_b1, b2_g2, b2_b2,
                        nullptr, x2fh, 1);

    // ---- final projection as MMA: C(16x128) = x2(4x2048, rows clamped) @ wf ----
    {
        const uint4* Fw = (const uint4*)(G + WFWF);
        const int kh = warp >> 3, q = warp & 7;
        float acc[2][4] = {};
        int rlo = min(r, 3);
        const __half* AhL = x2fh + rlo * STH_F + 4 * c;
        const __half* AhH = x2fh + 3   * STH_F + 4 * c;   // rows r+8 all clamp to 3
        for (int ktp = 0; ktp < 32; ktp++) {
            int ktg = kh * 32 + ktp;
            uint4 bb0 = Fw[((2 * q)     * 64 + ktg) * 32 + lane];
            uint4 bb1 = Fw[((2 * q + 1) * 64 + ktg) * 32 + lane];
            #pragma unroll
            for (int kk = 0; kk < 2; kk++) {
                int g = (ktg * 2 + kk) * 16;
                uint2 lo = *(const uint2*)(AhL + g);
                uint2 hi = *(const uint2*)(AhH + g);
                mma16(acc[0], lo.x, hi.x, lo.y, hi.y, kk ? bb0.z : bb0.x, kk ? bb0.w : bb0.y);
                mma16(acc[1], lo.x, hi.x, lo.y, hi.y, kk ? bb1.z : bb1.x, kk ? bb1.w : bb1.y);
            }
        }
        float* scr = arena + S_O;   // 4 x 128 partial scratch
        if (kh == 1 && r < 4) {
            #pragma unroll
            for (int j = 0; j < 2; j++) {
                int n0 = (2 * q + j) * 8 + 2 * c;
                scr[r * 128 + n0]     = acc[j][0];
                scr[r * 128 + n0 + 1] = acc[j][1];
            }
        }
        __syncthreads();
        if (kh == 0 && r < 4) {
            int t = t0 + r;
            #pragma unroll
            for (int j = 0; j < 2; j++) {
                int n0 = (2 * q + j) * 8 + 2 * c;
                float v0 = acc[j][0] + scr[r * 128 + n0]     + bf[n0];
                float v1 = acc[j][1] + scr[r * 128 + n0 + 1] + bf[n0 + 1];
                out[((long)b * 128 + n0) * 128 + t]     = v0;
                out[((long)b * 128 + n0 + 1) * 128 + t] = v1;
            }
        }
    }
}

extern "C" void kernel_launch(void* const* d_in, const int* in_sizes, int n_in,
                              void* d_out, int out_size) {
    (void)in_sizes; (void)n_in; (void)out_size;
    const float* p[30];
    for (int i = 0; i < 30; i++) p[i] = (const float*)d_in[i];

    static bool attr_set = false;
    if (!attr_set) {
        cudaFuncSetAttribute(encoder_kernel,
                             cudaFuncAttributeMaxDynamicSharedMemorySize,
                             ARENA_FLOATS * (int)sizeof(float));
        attr_set = true;
    }

    prep_weights<<<(FRAG_TOTAL + 255) / 256, 256>>>(
        p[2], p[3], p[4], p[5],          // b1 wq wk wv wo
        p[7], p[9],                      // b1 ff1 ff2
        p[15], p[16], p[17], p[18],      // b2 wq wk wv wo
        p[20], p[22],                    // b2 ff1 ff2
        p[28]);                          // wf

    encoder_kernel<<<2048, NT, ARENA_FLOATS * sizeof(float)>>>(
        p[0], p[1],
        p[6],  p[8],  p[10], p[11], p[12], p[13], p[14],   // b1 biases/LN
        p[19], p[21], p[23], p[24], p[25], p[26], p[27],   // b2 biases/LN
        p[29],
        (float*)d_out);
}

// round 9
// speedup vs baseline: 7.4627x; 1.1333x over previous
#include <cuda_runtime.h>
#include <cuda_fp16.h>

#define NT 512

// ---------------- fp16 fragment-linear weight scratch ----------------
// m16n8k16 f16 B-fragments, k32 (2 k16 tiles) packed per uint4:
//   uint index = (nt*KTP + ktp)*128 + lane*4 + kk*2 + reg   (each uint = half2)
//   kbase = (2*ktp+kk)*16 + reg*8 + 2*(lane&3) ; n = nt*8 + (lane>>2)
#define FRAG_TOTAL 346112
__device__ __align__(16) unsigned int g_wfrag[FRAG_TOTAL];

#define WFQ1 0
#define WFK1 14336
#define WFV1 28672
#define WFO1 43008
#define WF11 51200
#define WF21 83968
#define WFQ2 116736
#define WFK2 124928
#define WFV2 133120
#define WFO2 141312
#define WF12 149504
#define WF22 182272
#define WFWF 215040

// big intermediates (L2-resident)
__device__ __align__(16) __half g_P[8192 * 1152];    // block1 qkv projections per (b,tc)
__device__ __align__(16) __half g_x2[8192 * 2048];   // x2 flat, permuted fragment layout

__global__ void prep_weights(const float* __restrict__ q1, const float* __restrict__ k1,
                             const float* __restrict__ v1, const float* __restrict__ o1,
                             const float* __restrict__ f11, const float* __restrict__ f21,
                             const float* __restrict__ q2, const float* __restrict__ k2,
                             const float* __restrict__ v2, const float* __restrict__ o2,
                             const float* __restrict__ f12, const float* __restrict__ f22,
                             const float* __restrict__ wf) {
    int e = blockIdx.x * blockDim.x + threadIdx.x;
    if (e >= FRAG_TOTAL) return;
    const int offs[14] = {0,14336,28672,43008,51200,83968,116736,124928,133120,
                          141312,149504,182272,215040,346112};
    const int Kr[13] = {196,196,196,128,128,512,128,128,128,128,128,512,2048};
    const int Nn[13] = {128,128,128,128,512,128,128,128,128,128,512,128,128};
    int m = 0;
    while (e >= offs[m + 1]) m++;
    const float* W =
        m==0?q1: m==1?k1: m==2?v1: m==3?o1: m==4?f11: m==5?f21:
        m==6?q2: m==7?k2: m==8?v2: m==9?o2: m==10?f12: m==11?f22: wf;
    int l = e - offs[m];
    int N = Nn[m], K = Kr[m];
    int KTPm = (offs[m + 1] - offs[m]) / (16 * N);
    int blk = l >> 7, li = l & 127;
    int lane = li >> 2, kk = (li >> 1) & 1, reg = li & 1;
    int nt = blk / KTPm, ktp = blk - nt * KTPm;
    int kbase = (2 * ktp + kk) * 16 + reg * 8 + 2 * (lane & 3);
    int n = nt * 8 + (lane >> 2);
    float wa = (kbase     < K) ? W[(long)kbase * N + n] : 0.f;
    float wb = (kbase + 1 < K) ? W[(long)(kbase + 1) * N + n] : 0.f;
    __half2 h2 = __floats2half2_rn(wa, wb);
    g_wfrag[e] = *reinterpret_cast<unsigned int*>(&h2);
}

// ---------------- layout helpers ----------------
__device__ __forceinline__ int permc(int l) {
    return (l < 8) ? ((l >> 1) * 4 + (l & 1)) : (((l - 8) >> 1) * 4 + 2 + (l & 1));
}
__device__ __forceinline__ int pcol(int col) {
    return (col >> 4) * 16 + permc(col & 15);
}

__device__ __forceinline__ void mma16(float* d, unsigned a0, unsigned a1,
                                      unsigned a2, unsigned a3,
                                      unsigned b0, unsigned b1) {
    asm volatile("mma.sync.aligned.m16n8k16.row.col.f32.f16.f16.f32 "
                 "{%0,%1,%2,%3}, {%4,%5,%6,%7}, {%8,%9}, {%0,%1,%2,%3};"
                 : "+f"(d[0]), "+f"(d[1]), "+f"(d[2]), "+f"(d[3])
                 : "r"(a0), "r"(a1), "r"(a2), "r"(a3), "r"(b0), "r"(b1));
}

// ================= kernel 0: per-timestep QKV projections for block 1 ======
// P[b*128+tc][m*128+n] = sum_c xin[b,c,tc] * W_m[c,n], m in {q,k,v}
#define STH_P 240   // halves; 480B/8=60? bytes/8 = S/4 mod 16: 240/4=60 mod16=12 OK
__global__ void __launch_bounds__(NT, 1)
qkv1_kernel(const float* __restrict__ enc, const float* __restrict__ off) {
    extern __shared__ __half xsm[];
    const int tid = threadIdx.x;
    const int warp = tid >> 5, lane = tid & 31;
    const int r = lane >> 2, c = lane & 3;
    const int b = blockIdx.x;

    // stage xin: rows t (128), cols cc (224, >=196 zero), permuted, stride 240
    for (int i = tid; i < 224 * 128; i += NT) {
        int cc = i >> 7, t = i & 127;
        float val = 0.f;
        if (cc < 112)      val = enc[((long)b * 112 + cc) * 128 + t];
        else if (cc < 196) val = off[b * 84 + (cc - 112)];
        xsm[t * STH_P + pcol(cc)] = __float2half_rn(val);
    }
    __syncthreads();

    const uint4* Fq = (const uint4*)(g_wfrag + WFQ1);
    const uint4* Fk = (const uint4*)(g_wfrag + WFK1);
    const uint4* Fv = (const uint4*)(g_wfrag + WFV1);
    const int n0 = warp * 8 + 2 * c;
    __half* Pb = g_P + (long)b * 128 * 1152;

    for (int mt = 0; mt < 8; mt++) {
        float aq[4] = {}, ak[4] = {}, av[4] = {};
        const __half* Ah = xsm + (mt * 16 + r) * STH_P + 4 * c;
        #pragma unroll
        for (int ktp = 0; ktp < 7; ktp++) {
            uint4 bq = Fq[(warp * 7 + ktp) * 32 + lane];
            uint4 bk = Fk[(warp * 7 + ktp) * 32 + lane];
            uint4 bv = Fv[(warp * 7 + ktp) * 32 + lane];
            #pragma unroll
            for (int kk = 0; kk < 2; kk++) {
                int g = (ktp * 2 + kk) * 16;
                uint2 lo = *(const uint2*)(Ah + g);
                uint2 hi = *(const uint2*)(Ah + 8 * STH_P + g);
                mma16(aq, lo.x, hi.x, lo.y, hi.y, kk ? bq.z : bq.x, kk ? bq.w : bq.y);
                mma16(ak, lo.x, hi.x, lo.y, hi.y, kk ? bk.z : bk.x, kk ? bk.w : bk.y);
                mma16(av, lo.x, hi.x, lo.y, hi.y, kk ? bv.z : bv.x, kk ? bv.w : bv.y);
            }
        }
        int row0 = mt * 16 + r;
        __half* P0 = Pb + (long)row0 * 1152 + n0;
        __half* P1 = Pb + (long)(row0 + 8) * 1152 + n0;
        *(__half2*)(P0)       = __floats2half2_rn(aq[0], aq[1]);
        *(__half2*)(P1)       = __floats2half2_rn(aq[2], aq[3]);
        *(__half2*)(P0 + 128) = __floats2half2_rn(ak[0], ak[1]);
        *(__half2*)(P1 + 128) = __floats2half2_rn(ak[2], ak[3]);
        *(__half2*)(P0 + 256) = __floats2half2_rn(av[0], av[1]);
        *(__half2*)(P1 + 256) = __floats2half2_rn(av[2], av[3]);
    }
}

// ---------------- encoder shared arena ----------------
#define ST_X    136
#define STH_X   144
#define STH_FF  272
#define S_O     0
#define S_H     8704
#define S_X1    17408
#define S_HALF  26112
#define H_OH    0
#define H_HH    9216
#define H_X1H   18432
#define H_FFH   27648
#define ARENA_FLOATS 48640

__device__ __forceinline__ void warp_reduce2(float& s, float& s2) {
    #pragma unroll
    for (int off = 16; off; off >>= 1) {
        s  += __shfl_xor_sync(0xffffffffu, s,  off);
        s2 += __shfl_xor_sync(0xffffffffu, s2, off);
    }
}

// LayerNorm over 64 rows x 128 cols. Optional fp32 dst, fp16 smem dst (permuted),
// fp16 GLOBAL dst (flat x2 layout: gdst[sq*2048 + pcol(w*128+col)]).
__device__ void lnorm64(const float* __restrict__ src, const float* __restrict__ resid,
                        const float* __restrict__ g, const float* __restrict__ bta,
                        const float* __restrict__ dst_add,
                        float* __restrict__ dstF, __half* __restrict__ dstH,
                        __half* __restrict__ gdst) {
    int warp = threadIdx.x >> 5, lane = threadIdx.x & 31;
    #pragma unroll
    for (int rr = 0; rr < 4; rr++) {
        int row = warp + rr * 16;
        float v[4]; float s = 0.f, s2 = 0.f;
        #pragma unroll
        for (int i = 0; i < 4; i++) {
            int col = lane + 32 * i;
            float x = src[row * ST_X + col];
            if (resid) x += resid[row * ST_X + col];
            v[i] = x; s += x; s2 += x * x;
        }
        warp_reduce2(s, s2);
        float m   = s * (1.f / 128.f);
        float var = fmaxf(s2 * (1.f / 128.f) - m * m, 0.f);
        float inv = rsqrtf(var + 1e-5f);
        #pragma unroll
        for (int i = 0; i < 4; i++) {
            int col = lane + 32 * i;
            float val = (v[i] - m) * inv * g[col] + bta[col];
            if (dst_add) val += dst_add[row * ST_X + col];
            if (dstF) dstF[row * ST_X + col] = val;
            if (dstH) dstH[row * STH_X + pcol(col)] = __float2half_rn(val);
            if (gdst) {
                int sq = row >> 4, w = row & 15;
                gdst[(long)sq * 2048 + pcol(w * 128 + col)] = __float2half_rn(val);
            }
        }
    }
}

// One transformer block over 4 sequences. GATHER: q/k/v loaded from g_P.
template<bool GATHER>
__device__ void run_block(float* arena, const __half* __restrict__ Xh,
                          const __half* __restrict__ Pbase, int t0,
                          const float* __restrict__ resid,
                          const uint4* __restrict__ Fq, const uint4* __restrict__ Fk,
                          const uint4* __restrict__ Fv, const uint4* __restrict__ Fo,
                          const uint4* __restrict__ F1, const uint4* __restrict__ F2,
                          const float* __restrict__ bo, const float* __restrict__ bf1,
                          const float* __restrict__ bf2,
                          const float* __restrict__ g1, const float* __restrict__ b1v,
                          const float* __restrict__ g2, const float* __restrict__ b2v,
                          float* __restrict__ dstF, __half* __restrict__ dstH,
                          __half* __restrict__ gdst) {
    const int warp = threadIdx.x >> 5, lane = threadIdx.x & 31;
    const int r = lane >> 2, c = lane & 3;
    float*  o   = arena + S_O;
    float*  h   = arena + S_H;
    __half* hb  = (__half*)(arena + S_HALF);
    __half* oh  = hb + H_OH;
    __half* hh  = hb + H_HH;
    __half* ffh = hb + H_FFH;

    // ---- QKV + register attention ----
    {
        float aq[4][4], ak[4][4], av[4][4];
        if (GATHER) {
            const int n0 = warp * 8 + 2 * c;
            #pragma unroll
            for (int s = 0; s < 4; s++) {
                int t = t0 + s;
                int tcA = min(max(t + r - 8, 0), 127);
                int tcB = min(max(t + r, 0), 127);      // w = r+8
                const __half* Pa = Pbase + (long)tcA * 1152 + n0;
                const __half* Pc = Pbase + (long)tcB * 1152 + n0;
                float2 f;
                f = __half22float2(*(const __half2*)(Pa));        aq[s][0]=f.x; aq[s][1]=f.y;
                f = __half22float2(*(const __half2*)(Pc));        aq[s][2]=f.x; aq[s][3]=f.y;
                f = __half22float2(*(const __half2*)(Pa + 128));  ak[s][0]=f.x; ak[s][1]=f.y;
                f = __half22float2(*(const __half2*)(Pc + 128));  ak[s][2]=f.x; ak[s][3]=f.y;
                f = __half22float2(*(const __half2*)(Pa + 256));  av[s][0]=f.x; av[s][1]=f.y;
                f = __half22float2(*(const __half2*)(Pc + 256));  av[s][2]=f.x; av[s][3]=f.y;
            }
        } else {
            #pragma unroll
            for (int s = 0; s < 4; s++)
                #pragma unroll
                for (int i = 0; i < 4; i++) { aq[s][i]=0.f; ak[s][i]=0.f; av[s][i]=0.f; }
            const __half* Ah = Xh + r * STH_X + 4 * c;
            #pragma unroll
            for (int ktp = 0; ktp < 4; ktp++) {
                uint4 bq = Fq[(warp * 4 + ktp) * 32 + lane];
                uint4 bk = Fk[(warp * 4 + ktp) * 32 + lane];
                uint4 bv = Fv[(warp * 4 + ktp) * 32 + lane];
                #pragma unroll
                for (int s = 0; s < 4; s++) {
                    const __half* As = Ah + s * 16 * STH_X;
                    #pragma unroll
                    for (int kk = 0; kk < 2; kk++) {
                        int g = (ktp * 2 + kk) * 16;
                        uint2 lo = *(const uint2*)(As + g);
                        uint2 hi = *(const uint2*)(As + 8 * STH_X + g);
                        mma16(aq[s], lo.x, hi.x, lo.y, hi.y, kk ? bq.z : bq.x, kk ? bq.w : bq.y);
                        mma16(ak[s], lo.x, hi.x, lo.y, hi.y, kk ? bk.z : bk.x, kk ? bk.w : bk.y);
                        mma16(av[s], lo.x, hi.x, lo.y, hi.y, kk ? bv.z : bv.x, kk ? bv.w : bv.y);
                    }
                }
            }
        }
        const float scale = 0.70710678118654752f;
        int gpos = (warp >> 1) * 16 + 4 * c + 2 * (warp & 1);
        #pragma unroll
        for (int s = 0; s < 4; s++) {
            float sumA = 0.f, sumB = 0.f;
            float oA0 = 0.f, oA1 = 0.f, oB0 = 0.f, oB1 = 0.f;
            #pragma unroll
            for (int rp = 0; rp < 8; rp++) {
                int src = rp * 4 + c;
                float k00 = __shfl_sync(0xffffffffu, ak[s][0], src);
                float k01 = __shfl_sync(0xffffffffu, ak[s][1], src);
                float k10 = __shfl_sync(0xffffffffu, ak[s][2], src);
                float k11 = __shfl_sync(0xffffffffu, ak[s][3], src);
                float v00 = __shfl_sync(0xffffffffu, av[s][0], src);
                float v01 = __shfl_sync(0xffffffffu, av[s][1], src);
                float v10 = __shfl_sync(0xffffffffu, av[s][2], src);
                float v11 = __shfl_sync(0xffffffffu, av[s][3], src);
                float eA0 = __expf((aq[s][0] * k00 + aq[s][1] * k01) * scale);
                float eA1 = __expf((aq[s][0] * k10 + aq[s][1] * k11) * scale);
                float eB0 = __expf((aq[s][2] * k00 + aq[s][3] * k01) * scale);
                float eB1 = __expf((aq[s][2] * k10 + aq[s][3] * k11) * scale);
                sumA += eA0 + eA1; sumB += eB0 + eB1;
                oA0 += eA0 * v00 + eA1 * v10; oA1 += eA0 * v01 + eA1 * v11;
                oB0 += eB0 * v00 + eB1 * v10; oB1 += eB0 * v01 + eB1 * v11;
            }
            float iA = 1.f / sumA, iB = 1.f / sumB;
            *(__half2*)(oh + (s * 16 + r) * STH_X + gpos)     = __floats2half2_rn(oA0 * iA, oA1 * iA);
            *(__half2*)(oh + (s * 16 + r + 8) * STH_X + gpos) = __floats2half2_rn(oB0 * iB, oB1 * iB);
        }
    }
    __syncthreads();

    const int sp = warp >> 3, q = warp & 7;

    // ---- WO: warp = (2 nt, 2 seq), KTP=4 ----
    {
        float acc[2][2][4] = {};
        const __half* Ah = oh + (sp * 32 + r) * STH_X + 4 * c;
        #pragma unroll
        for (int ktp = 0; ktp < 4; ktp++) {
            uint4 bb0 = Fo[((2 * q)     * 4 + ktp) * 32 + lane];
            uint4 bb1 = Fo[((2 * q + 1) * 4 + ktp) * 32 + lane];
            #pragma unroll
            for (int s = 0; s < 2; s++) {
                const __half* As = Ah + s * 16 * STH_X;
                #pragma unroll
                for (int kk = 0; kk < 2; kk++) {
                    int g = (ktp * 2 + kk) * 16;
                    uint2 lo = *(const uint2*)(As + g);
                    uint2 hi = *(const uint2*)(As + 8 * STH_X + g);
                    mma16(acc[0][s], lo.x, hi.x, lo.y, hi.y, kk ? bb0.z : bb0.x, kk ? bb0.w : bb0.y);
                    mma16(acc[1][s], lo.x, hi.x, lo.y, hi.y, kk ? bb1.z : bb1.x, kk ? bb1.w : bb1.y);
                }
            }
        }
        #pragma unroll
        for (int j = 0; j < 2; j++) {
            int n0 = (2 * q + j) * 8 + 2 * c;
            float2 bb = *(const float2*)(bo + n0);
            #pragma unroll
            for (int s = 0; s < 2; s++) {
                int row = (sp * 2 + s) * 16 + r;
                *(float2*)(h + row * ST_X + n0)       = make_float2(acc[j][s][0] + bb.x, acc[j][s][1] + bb.y);
                *(float2*)(h + (row + 8) * ST_X + n0) = make_float2(acc[j][s][2] + bb.x, acc[j][s][3] + bb.y);
            }
        }
    }
    __syncthreads();

    lnorm64(h, resid, g1, b1v, nullptr, h, hh, nullptr);
    __syncthreads();

    // ---- FF in two N=256 halves ----
    float accF2[2][2][4] = {};
    #pragma unroll
    for (int half = 0; half < 2; half++) {
        {   // FF1: warp = (4 nt local, 2 seq), KTP=4
            float a1a[4][2][4] = {};
            const __half* Ah = hh + (sp * 32 + r) * STH_X + 4 * c;
            #pragma unroll
            for (int ktp = 0; ktp < 4; ktp++) {
                uint4 bb[4];
                #pragma unroll
                for (int j = 0; j < 4; j++)
                    bb[j] = F1[((half * 32 + q * 4 + j) * 4 + ktp) * 32 + lane];
                #pragma unroll
                for (int s = 0; s < 2; s++) {
                    const __half* As = Ah + s * 16 * STH_X;
                    #pragma unroll
                    for (int kk = 0; kk < 2; kk++) {
                        int g = (ktp * 2 + kk) * 16;
                        uint2 lo = *(const uint2*)(As + g);
                        uint2 hi = *(const uint2*)(As + 8 * STH_X + g);
                        #pragma unroll
                        for (int j = 0; j < 4; j++)
                            mma16(a1a[j][s], lo.x, hi.x, lo.y, hi.y,
                                  kk ? bb[j].z : bb[j].x, kk ? bb[j].w : bb[j].y);
                    }
                }
            }
            #pragma unroll
            for (int j = 0; j < 4; j++) {
                int ntl = q * 4 + j;
                int gpos = (ntl >> 1) * 16 + 4 * c + 2 * (ntl & 1);
                float2 bb = *(const float2*)(bf1 + half * 256 + ntl * 8 + 2 * c);
                #pragma unroll
                for (int s = 0; s < 2; s++) {
                    int row = (sp * 2 + s) * 16 + r;
                    *(__half2*)(ffh + row * STH_FF + gpos) =
                        __floats2half2_rn(fmaxf(a1a[j][s][0] + bb.x, 0.f), fmaxf(a1a[j][s][1] + bb.y, 0.f));
                    *(__half2*)(ffh + (row + 8) * STH_FF + gpos) =
                        __floats2half2_rn(fmaxf(a1a[j][s][2] + bb.x, 0.f), fmaxf(a1a[j][s][3] + bb.y, 0.f));
                }
            }
        }
        __syncthreads();
        {   // FF2: warp = (2 nt, 2 seq); local KTP=8, global 16
            const __half* Ah = ffh + (sp * 32 + r) * STH_FF + 4 * c;
            #pragma unroll
            for (int ktp = 0; ktp < 8; ktp++) {
                uint4 bb0 = F2[((2 * q)     * 16 + half * 8 + ktp) * 32 + lane];
                uint4 bb1 = F2[((2 * q + 1) * 16 + half * 8 + ktp) * 32 + lane];
                #pragma unroll
                for (int s = 0; s < 2; s++) {
                    const __half* As = Ah + s * 16 * STH_FF;
                    #pragma unroll
                    for (int kk = 0; kk < 2; kk++) {
                        int g = (ktp * 2 + kk) * 16;
                        uint2 lo = *(const uint2*)(As + g);
                        uint2 hi = *(const uint2*)(As + 8 * STH_FF + g);
                        mma16(accF2[0][s], lo.x, hi.x, lo.y, hi.y, kk ? bb0.z : bb0.x, kk ? bb0.w : bb0.y);
                        mma16(accF2[1][s], lo.x, hi.x, lo.y, hi.y, kk ? bb1.z : bb1.x, kk ? bb1.w : bb1.y);
                    }
                }
            }
        }
        __syncthreads();
    }
    #pragma unroll
    for (int j = 0; j < 2; j++) {
        int n0 = (2 * q + j) * 8 + 2 * c;
        float2 bb = *(const float2*)(bf2 + n0);
        #pragma unroll
        for (int s = 0; s < 2; s++) {
            int row = (sp * 2 + s) * 16 + r;
            *(float2*)(o + row * ST_X + n0)       = make_float2(accF2[j][s][0] + bb.x, accF2[j][s][1] + bb.y);
            *(float2*)(o + (row + 8) * ST_X + n0) = make_float2(accF2[j][s][2] + bb.x, accF2[j][s][3] + bb.y);
        }
    }
    __syncthreads();

    lnorm64(o, h, g2, b2v, resid, dstF, dstH, gdst);
    __syncthreads();
}

__global__ void __launch_bounds__(NT, 1)
encoder_kernel(const float* __restrict__ b1_bo, const float* __restrict__ b1_bf1,
               const float* __restrict__ b1_bf2,
               const float* __restrict__ b1_g1, const float* __restrict__ b1_b1,
               const float* __restrict__ b1_g2, const float* __restrict__ b1_b2,
               const float* __restrict__ b2_bo, const float* __restrict__ b2_bf1,
               const float* __restrict__ b2_bf2,
               const float* __restrict__ b2_g1, const float* __restrict__ b2_b1,
               const float* __restrict__ b2_g2, const float* __restrict__ b2_b2) {
    extern __shared__ float arena[];
    const int b = blockIdx.x >> 5;
    const int t0 = (blockIdx.x & 31) << 2;

    __half* hb  = (__half*)(arena + S_HALF);
    __half* x1h = hb + H_X1H;
    float*  x1  = arena + S_X1;
    const __half* Pbase = g_P + (long)b * 128 * 1152;
    __half* gx2 = g_x2 + (long)(b * 128 + t0) * 2048;

    const unsigned* G = g_wfrag;
    // block 1: qkv gathered from g_P; out: x1 fp32 + x1h mirror
    run_block<true>(arena, nullptr, Pbase, t0, nullptr,
                    nullptr, nullptr, nullptr, (const uint4*)(G + WFO1),
                    (const uint4*)(G + WF11), (const uint4*)(G + WF21),
                    b1_bo, b1_bf1, b1_bf2, b1_g1, b1_b1, b1_g2, b1_b2,
                    x1, x1h, nullptr);

    // block 2: qkv MMA from x1h; x2 = x1 + blk(x1) written to g_x2
    run_block<false>(arena, x1h, nullptr, 0, x1,
                     (const uint4*)(G + WFQ2), (const uint4*)(G + WFK2),
                     (const uint4*)(G + WFV2), (const uint4*)(G + WFO2),
                     (const uint4*)(G + WF12), (const uint4*)(G + WF22),
                     b2_bo, b2_bf1, b2_bf2, b2_g1, b2_b1, b2_g2, b2_b2,
                     nullptr, nullptr, gx2);
}

// ================= kernel 2: final projection GEMM =========================
#define STH_F 2064
__global__ void __launch_bounds__(256)
final_kernel(const float* __restrict__ bf, float* __restrict__ out) {
    extern __shared__ __half fs[];
    const int tid = threadIdx.x;
    const int warp = tid >> 5, lane = tid & 31;
    const int r = lane >> 2, c = lane & 3;
    const int seq0 = blockIdx.x * 16;

    // stage A tile (16 x 2048) into smem at stride 2064 (coalesced uint4 copy)
    for (int i = tid; i < 4096; i += 256) {
        int row = i >> 8, cg = i & 255;
        const uint4* src = (const uint4*)(g_x2 + (long)(seq0 + row) * 2048) + cg;
        *((uint4*)(fs + row * STH_F) + cg) = *src;
    }
    __syncthreads();

    const uint4* Fw = (const uint4*)(g_wfrag + WFWF);
    float acc[2][4] = {};
    const __half* Ah = fs + r * STH_F + 4 * c;
    for (int ktg = 0; ktg < 64; ktg++) {
        uint4 bb0 = Fw[((2 * warp)     * 64 + ktg) * 32 + lane];
        uint4 bb1 = Fw[((2 * warp + 1) * 64 + ktg) * 32 + lane];
        #pragma unroll
        for (int kk = 0; kk < 2; kk++) {
            int g = (ktg * 2 + kk) * 16;
            uint2 lo = *(const uint2*)(Ah + g);
            uint2 hi = *(const uint2*)(Ah + 8 * STH_F + g);
            mma16(acc[0], lo.x, hi.x, lo.y, hi.y, kk ? bb0.z : bb0.x, kk ? bb0.w : bb0.y);
            mma16(acc[1], lo.x, hi.x, lo.y, hi.y, kk ? bb1.z : bb1.x, kk ? bb1.w : bb1.y);
        }
    }
    const int b = seq0 >> 7;
    const int tbase = seq0 & 127;
    #pragma unroll
    for (int j = 0; j < 2; j++) {
        int n0 = (2 * warp + j) * 8 + 2 * c;
        float bf0 = bf[n0], bf1 = bf[n0 + 1];
        out[((long)b * 128 + n0)     * 128 + tbase + r]     = acc[j][0] + bf0;
        out[((long)b * 128 + n0 + 1) * 128 + tbase + r]     = acc[j][1] + bf1;
        out[((long)b * 128 + n0)     * 128 + tbase + r + 8] = acc[j][2] + bf0;
        out[((long)b * 128 + n0 + 1) * 128 + tbase + r + 8] = acc[j][3] + bf1;
    }
}

extern "C" void kernel_launch(void* const* d_in, const int* in_sizes, int n_in,
                              void* d_out, int out_size) {
    (void)in_sizes; (void)n_in; (void)out_size;
    const float* p[30];
    for (int i = 0; i < 30; i++) p[i] = (const float*)d_in[i];

    static bool attr_set = false;
    if (!attr_set) {
        cudaFuncSetAttribute(qkv1_kernel, cudaFuncAttributeMaxDynamicSharedMemorySize,
                             224 * 0 + 128 * STH_P * (int)sizeof(__half));
        cudaFuncSetAttribute(encoder_kernel, cudaFuncAttributeMaxDynamicSharedMemorySize,
                             ARENA_FLOATS * (int)sizeof(float));
        cudaFuncSetAttribute(final_kernel, cudaFuncAttributeMaxDynamicSharedMemorySize,
                             16 * STH_F * (int)sizeof(__half));
        attr_set = true;
    }

    prep_weights<<<(FRAG_TOTAL + 255) / 256, 256>>>(
        p[2], p[3], p[4], p[5], p[7], p[9],
        p[15], p[16], p[17], p[18], p[20], p[22], p[28]);

    qkv1_kernel<<<64, NT, 128 * STH_P * sizeof(__half)>>>(p[0], p[1]);

    encoder_kernel<<<2048, NT, ARENA_FLOATS * sizeof(float)>>>(
        p[6],  p[8],  p[10], p[11], p[12], p[13], p[14],
        p[19], p[21], p[23], p[24], p[25], p[26], p[27]);

    final_kernel<<<512, 256, 16 * STH_F * sizeof(__half)>>>(p[29], (float*)d_out);
}

// round 10
// speedup vs baseline: 7.4802x; 1.0023x over previous
#include <cuda_runtime.h>
#include <cuda_fp16.h>

#define NT 512

// ---------------- fp16 fragment-linear weight scratch ----------------
// m16n8k16 f16 B-fragments, k32 (2 k16 tiles) packed per uint4:
//   uint index = (nt*KTP + ktp)*128 + lane*4 + kk*2 + reg   (each uint = half2)
//   kbase = (2*ktp+kk)*16 + reg*8 + 2*(lane&3) ; n = nt*8 + (lane>>2)
#define FRAG_TOTAL 346112
__device__ __align__(16) unsigned int g_wfrag[FRAG_TOTAL];

#define WFQ1 0
#define WFK1 14336
#define WFV1 28672
#define WFO1 43008
#define WF11 51200
#define WF21 83968
#define WFQ2 116736
#define WFK2 124928
#define WFV2 133120
#define WFO2 141312
#define WF12 149504
#define WF22 182272
#define WFWF 215040

// big intermediates (L2-resident)
__device__ __align__(16) __half g_P[8192 * 1152];    // block1 qkv projections per (b,tc)
__device__ __align__(16) __half g_x2[8192 * 2048];   // x2 flat, permuted fragment layout

__global__ void prep_weights(const float* __restrict__ q1, const float* __restrict__ k1,
                             const float* __restrict__ v1, const float* __restrict__ o1,
                             const float* __restrict__ f11, const float* __restrict__ f21,
                             const float* __restrict__ q2, const float* __restrict__ k2,
                             const float* __restrict__ v2, const float* __restrict__ o2,
                             const float* __restrict__ f12, const float* __restrict__ f22,
                             const float* __restrict__ wf) {
    int e = blockIdx.x * blockDim.x + threadIdx.x;
    if (e >= FRAG_TOTAL) return;
    const int offs[14] = {0,14336,28672,43008,51200,83968,116736,124928,133120,
                          141312,149504,182272,215040,346112};
    const int Kr[13] = {196,196,196,128,128,512,128,128,128,128,128,512,2048};
    const int Nn[13] = {128,128,128,128,512,128,128,128,128,128,512,128,128};
    int m = 0;
    while (e >= offs[m + 1]) m++;
    const float* W =
        m==0?q1: m==1?k1: m==2?v1: m==3?o1: m==4?f11: m==5?f21:
        m==6?q2: m==7?k2: m==8?v2: m==9?o2: m==10?f12: m==11?f22: wf;
    int l = e - offs[m];
    int N = Nn[m], K = Kr[m];
    int KTPm = (offs[m + 1] - offs[m]) / (16 * N);
    int blk = l >> 7, li = l & 127;
    int lane = li >> 2, kk = (li >> 1) & 1, reg = li & 1;
    int nt = blk / KTPm, ktp = blk - nt * KTPm;
    int kbase = (2 * ktp + kk) * 16 + reg * 8 + 2 * (lane & 3);
    int n = nt * 8 + (lane >> 2);
    float wa = (kbase     < K) ? W[(long)kbase * N + n] : 0.f;
    float wb = (kbase + 1 < K) ? W[(long)(kbase + 1) * N + n] : 0.f;
    __half2 h2 = __floats2half2_rn(wa, wb);
    g_wfrag[e] = *reinterpret_cast<unsigned int*>(&h2);
}

// ---------------- layout helpers ----------------
__device__ __forceinline__ int permc(int l) {
    return (l < 8) ? ((l >> 1) * 4 + (l & 1)) : (((l - 8) >> 1) * 4 + 2 + (l & 1));
}
__device__ __forceinline__ int pcol(int col) {
    return (col >> 4) * 16 + permc(col & 15);
}

__device__ __forceinline__ void mma16(float* d, unsigned a0, unsigned a1,
                                      unsigned a2, unsigned a3,
                                      unsigned b0, unsigned b1) {
    asm volatile("mma.sync.aligned.m16n8k16.row.col.f32.f16.f16.f32 "
                 "{%0,%1,%2,%3}, {%4,%5,%6,%7}, {%8,%9}, {%0,%1,%2,%3};"
                 : "+f"(d[0]), "+f"(d[1]), "+f"(d[2]), "+f"(d[3])
                 : "r"(a0), "r"(a1), "r"(a2), "r"(a3), "r"(b0), "r"(b1));
}

// ================= kernel 0: per-timestep QKV projections for block 1 ======
#define STH_P 240
__global__ void __launch_bounds__(NT, 1)
qkv1_kernel(const float* __restrict__ enc, const float* __restrict__ off) {
    extern __shared__ __half xsm[];
    const int tid = threadIdx.x;
    const int warp = tid >> 5, lane = tid & 31;
    const int r = lane >> 2, c = lane & 3;
    const int b = blockIdx.x;

    for (int i = tid; i < 224 * 128; i += NT) {
        int cc = i >> 7, t = i & 127;
        float val = 0.f;
        if (cc < 112)      val = enc[((long)b * 112 + cc) * 128 + t];
        else if (cc < 196) val = off[b * 84 + (cc - 112)];
        xsm[t * STH_P + pcol(cc)] = __float2half_rn(val);
    }
    __syncthreads();

    const uint4* Fq = (const uint4*)(g_wfrag + WFQ1);
    const uint4* Fk = (const uint4*)(g_wfrag + WFK1);
    const uint4* Fv = (const uint4*)(g_wfrag + WFV1);
    const int n0 = warp * 8 + 2 * c;
    __half* Pb = g_P + (long)b * 128 * 1152;

    for (int mt = 0; mt < 8; mt++) {
        float aq[4] = {}, ak[4] = {}, av[4] = {};
        const __half* Ah = xsm + (mt * 16 + r) * STH_P + 4 * c;
        #pragma unroll
        for (int ktp = 0; ktp < 7; ktp++) {
            uint4 bq = Fq[(warp * 7 + ktp) * 32 + lane];
            uint4 bk = Fk[(warp * 7 + ktp) * 32 + lane];
            uint4 bv = Fv[(warp * 7 + ktp) * 32 + lane];
            #pragma unroll
            for (int kk = 0; kk < 2; kk++) {
                int g = (ktp * 2 + kk) * 16;
                uint2 lo = *(const uint2*)(Ah + g);
                uint2 hi = *(const uint2*)(Ah + 8 * STH_P + g);
                mma16(aq, lo.x, hi.x, lo.y, hi.y, kk ? bq.z : bq.x, kk ? bq.w : bq.y);
                mma16(ak, lo.x, hi.x, lo.y, hi.y, kk ? bk.z : bk.x, kk ? bk.w : bk.y);
                mma16(av, lo.x, hi.x, lo.y, hi.y, kk ? bv.z : bv.x, kk ? bv.w : bv.y);
            }
        }
        int row0 = mt * 16 + r;
        __half* P0 = Pb + (long)row0 * 1152 + n0;
        __half* P1 = Pb + (long)(row0 + 8) * 1152 + n0;
        *(__half2*)(P0)       = __floats2half2_rn(aq[0], aq[1]);
        *(__half2*)(P1)       = __floats2half2_rn(aq[2], aq[3]);
        *(__half2*)(P0 + 128) = __floats2half2_rn(ak[0], ak[1]);
        *(__half2*)(P1 + 128) = __floats2half2_rn(ak[2], ak[3]);
        *(__half2*)(P0 + 256) = __floats2half2_rn(av[0], av[1]);
        *(__half2*)(P1 + 256) = __floats2half2_rn(av[2], av[3]);
    }
}

// ---------------- encoder shared arena ----------------
#define ST_X    136
#define STH_X   144
#define STH_FF  528     // full-width ff buffer (64 x 512 cols)
#define S_O     0
#define S_H     8704
#define S_X1    17408
#define S_HALF  26112
#define H_OH    0
#define H_HH    9216
#define H_X1H   18432
#define H_FFH   27648   // 64 x 528 halves = 33792
#define ARENA_FLOATS 56832   // = 227,328 bytes

__device__ __forceinline__ void warp_reduce2(float& s, float& s2) {
    #pragma unroll
    for (int off = 16; off; off >>= 1) {
        s  += __shfl_xor_sync(0xffffffffu, s,  off);
        s2 += __shfl_xor_sync(0xffffffffu, s2, off);
    }
}

// LayerNorm over 64 rows x 128 cols.
__device__ void lnorm64(const float* __restrict__ src, const float* __restrict__ resid,
                        const float* __restrict__ g, const float* __restrict__ bta,
                        const float* __restrict__ dst_add,
                        float* __restrict__ dstF, __half* __restrict__ dstH,
                        __half* __restrict__ gdst) {
    int warp = threadIdx.x >> 5, lane = threadIdx.x & 31;
    #pragma unroll
    for (int rr = 0; rr < 4; rr++) {
        int row = warp + rr * 16;
        float v[4]; float s = 0.f, s2 = 0.f;
        #pragma unroll
        for (int i = 0; i < 4; i++) {
            int col = lane + 32 * i;
            float x = src[row * ST_X + col];
            if (resid) x += resid[row * ST_X + col];
            v[i] = x; s += x; s2 += x * x;
        }
        warp_reduce2(s, s2);
        float m   = s * (1.f / 128.f);
        float var = fmaxf(s2 * (1.f / 128.f) - m * m, 0.f);
        float inv = rsqrtf(var + 1e-5f);
        #pragma unroll
        for (int i = 0; i < 4; i++) {
            int col = lane + 32 * i;
            float val = (v[i] - m) * inv * g[col] + bta[col];
            if (dst_add) val += dst_add[row * ST_X + col];
            if (dstF) dstF[row * ST_X + col] = val;
            if (dstH) dstH[row * STH_X + pcol(col)] = __float2half_rn(val);
            if (gdst) {
                int sq = row >> 4, w = row & 15;
                gdst[(long)sq * 2048 + pcol(w * 128 + col)] = __float2half_rn(val);
            }
        }
    }
}

// One transformer block over 4 sequences. GATHER: q/k/v loaded from g_P.
template<bool GATHER>
__device__ void run_block(float* arena, const __half* __restrict__ Xh,
                          const __half* __restrict__ Pbase, int t0,
                          const float* __restrict__ resid,
                          const uint4* __restrict__ Fq, const uint4* __restrict__ Fk,
                          const uint4* __restrict__ Fv, const uint4* __restrict__ Fo,
                          const uint4* __restrict__ F1, const uint4* __restrict__ F2,
                          const float* __restrict__ bo, const float* __restrict__ bf1,
                          const float* __restrict__ bf2,
                          const float* __restrict__ g1, const float* __restrict__ b1v,
                          const float* __restrict__ g2, const float* __restrict__ b2v,
                          float* __restrict__ dstF, __half* __restrict__ dstH,
                          __half* __restrict__ gdst) {
    const int warp = threadIdx.x >> 5, lane = threadIdx.x & 31;
    const int r = lane >> 2, c = lane & 3;
    float*  o   = arena + S_O;
    float*  h   = arena + S_H;
    __half* hb  = (__half*)(arena + S_HALF);
    __half* oh  = hb + H_OH;
    __half* hh  = hb + H_HH;
    __half* ffh = hb + H_FFH;

    // ---- QKV + register attention ----
    {
        float aq[4][4], ak[4][4], av[4][4];
        if (GATHER) {
            const int n0 = warp * 8 + 2 * c;
            #pragma unroll
            for (int s = 0; s < 4; s++) {
                int t = t0 + s;
                int tcA = min(max(t + r - 8, 0), 127);
                int tcB = min(max(t + r, 0), 127);
                const __half* Pa = Pbase + (long)tcA * 1152 + n0;
                const __half* Pc = Pbase + (long)tcB * 1152 + n0;
                float2 f;
                f = __half22float2(*(const __half2*)(Pa));        aq[s][0]=f.x; aq[s][1]=f.y;
                f = __half22float2(*(const __half2*)(Pc));        aq[s][2]=f.x; aq[s][3]=f.y;
                f = __half22float2(*(const __half2*)(Pa + 128));  ak[s][0]=f.x; ak[s][1]=f.y;
                f = __half22float2(*(const __half2*)(Pc + 128));  ak[s][2]=f.x; ak[s][3]=f.y;
                f = __half22float2(*(const __half2*)(Pa + 256));  av[s][0]=f.x; av[s][1]=f.y;
                f = __half22float2(*(const __half2*)(Pc + 256));  av[s][2]=f.x; av[s][3]=f.y;
            }
        } else {
            #pragma unroll
            for (int s = 0; s < 4; s++)
                #pragma unroll
                for (int i = 0; i < 4; i++) { aq[s][i]=0.f; ak[s][i]=0.f; av[s][i]=0.f; }
            const __half* Ah = Xh + r * STH_X + 4 * c;
            #pragma unroll
            for (int ktp = 0; ktp < 4; ktp++) {
                uint4 bq = Fq[(warp * 4 + ktp) * 32 + lane];
                uint4 bk = Fk[(warp * 4 + ktp) * 32 + lane];
                uint4 bv = Fv[(warp * 4 + ktp) * 32 + lane];
                #pragma unroll
                for (int s = 0; s < 4; s++) {
                    const __half* As = Ah + s * 16 * STH_X;
                    #pragma unroll
                    for (int kk = 0; kk < 2; kk++) {
                        int g = (ktp * 2 + kk) * 16;
                        uint2 lo = *(const uint2*)(As + g);
                        uint2 hi = *(const uint2*)(As + 8 * STH_X + g);
                        mma16(aq[s], lo.x, hi.x, lo.y, hi.y, kk ? bq.z : bq.x, kk ? bq.w : bq.y);
                        mma16(ak[s], lo.x, hi.x, lo.y, hi.y, kk ? bk.z : bk.x, kk ? bk.w : bk.y);
                        mma16(av[s], lo.x, hi.x, lo.y, hi.y, kk ? bv.z : bv.x, kk ? bv.w : bv.y);
                    }
                }
            }
        }
        const float scale = 0.70710678118654752f;
        int gpos = (warp >> 1) * 16 + 4 * c + 2 * (warp & 1);
        #pragma unroll
        for (int s = 0; s < 4; s++) {
            float sumA = 0.f, sumB = 0.f;
            float oA0 = 0.f, oA1 = 0.f, oB0 = 0.f, oB1 = 0.f;
            #pragma unroll
            for (int rp = 0; rp < 8; rp++) {
                int src = rp * 4 + c;
                float k00 = __shfl_sync(0xffffffffu, ak[s][0], src);
                float k01 = __shfl_sync(0xffffffffu, ak[s][1], src);
                float k10 = __shfl_sync(0xffffffffu, ak[s][2], src);
                float k11 = __shfl_sync(0xffffffffu, ak[s][3], src);
                float v00 = __shfl_sync(0xffffffffu, av[s][0], src);
                float v01 = __shfl_sync(0xffffffffu, av[s][1], src);
                float v10 = __shfl_sync(0xffffffffu, av[s][2], src);
                float v11 = __shfl_sync(0xffffffffu, av[s][3], src);
                float eA0 = __expf((aq[s][0] * k00 + aq[s][1] * k01) * scale);
                float eA1 = __expf((aq[s][0] * k10 + aq[s][1] * k11) * scale);
                float eB0 = __expf((aq[s][2] * k00 + aq[s][3] * k01) * scale);
                float eB1 = __expf((aq[s][2] * k10 + aq[s][3] * k11) * scale);
                sumA += eA0 + eA1; sumB += eB0 + eB1;
                oA0 += eA0 * v00 + eA1 * v10; oA1 += eA0 * v01 + eA1 * v11;
                oB0 += eB0 * v00 + eB1 * v10; oB1 += eB0 * v01 + eB1 * v11;
            }
            float iA = 1.f / sumA, iB = 1.f / sumB;
            *(__half2*)(oh + (s * 16 + r) * STH_X + gpos)     = __floats2half2_rn(oA0 * iA, oA1 * iA);
            *(__half2*)(oh + (s * 16 + r + 8) * STH_X + gpos) = __floats2half2_rn(oB0 * iB, oB1 * iB);
        }
    }
    __syncthreads();

    const int sp = warp >> 3, q = warp & 7;

    // ---- WO: warp = (2 nt, 2 seq), KTP=4 ----
    {
        float acc[2][2][4] = {};
        const __half* Ah = oh + (sp * 32 + r) * STH_X + 4 * c;
        #pragma unroll
        for (int ktp = 0; ktp < 4; ktp++) {
            uint4 bb0 = Fo[((2 * q)     * 4 + ktp) * 32 + lane];
            uint4 bb1 = Fo[((2 * q + 1) * 4 + ktp) * 32 + lane];
            #pragma unroll
            for (int s = 0; s < 2; s++) {
                const __half* As = Ah + s * 16 * STH_X;
                #pragma unroll
                for (int kk = 0; kk < 2; kk++) {
                    int g = (ktp * 2 + kk) * 16;
                    uint2 lo = *(const uint2*)(As + g);
                    uint2 hi = *(const uint2*)(As + 8 * STH_X + g);
                    mma16(acc[0][s], lo.x, hi.x, lo.y, hi.y, kk ? bb0.z : bb0.x, kk ? bb0.w : bb0.y);
                    mma16(acc[1][s], lo.x, hi.x, lo.y, hi.y, kk ? bb1.z : bb1.x, kk ? bb1.w : bb1.y);
                }
            }
        }
        #pragma unroll
        for (int j = 0; j < 2; j++) {
            int n0 = (2 * q + j) * 8 + 2 * c;
            float2 bb = *(const float2*)(bo + n0);
            #pragma unroll
            for (int s = 0; s < 2; s++) {
                int row = (sp * 2 + s) * 16 + r;
                *(float2*)(h + row * ST_X + n0)       = make_float2(acc[j][s][0] + bb.x, acc[j][s][1] + bb.y);
                *(float2*)(h + (row + 8) * ST_X + n0) = make_float2(acc[j][s][2] + bb.x, acc[j][s][3] + bb.y);
            }
        }
    }
    __syncthreads();

    lnorm64(h, resid, g1, b1v, nullptr, h, hh, nullptr);
    __syncthreads();

    // ---- FF1: both N-halves into full-width ffh, ONE sync ----
    #pragma unroll
    for (int half = 0; half < 2; half++) {
        float a1a[4][2][4] = {};
        const __half* Ah = hh + (sp * 32 + r) * STH_X + 4 * c;
        #pragma unroll
        for (int ktp = 0; ktp < 4; ktp++) {
            uint4 bb[4];
            #pragma unroll
            for (int j = 0; j < 4; j++)
                bb[j] = F1[((half * 32 + q * 4 + j) * 4 + ktp) * 32 + lane];
            #pragma unroll
            for (int s = 0; s < 2; s++) {
                const __half* As = Ah + s * 16 * STH_X;
                #pragma unroll
                for (int kk = 0; kk < 2; kk++) {
                    int g = (ktp * 2 + kk) * 16;
                    uint2 lo = *(const uint2*)(As + g);
                    uint2 hi = *(const uint2*)(As + 8 * STH_X + g);
                    #pragma unroll
                    for (int j = 0; j < 4; j++)
                        mma16(a1a[j][s], lo.x, hi.x, lo.y, hi.y,
                              kk ? bb[j].z : bb[j].x, kk ? bb[j].w : bb[j].y);
                }
            }
        }
        #pragma unroll
        for (int j = 0; j < 4; j++) {
            int ntl = q * 4 + j;
            int gpos = half * 256 + (ntl >> 1) * 16 + 4 * c + 2 * (ntl & 1);
            float2 bb = *(const float2*)(bf1 + half * 256 + ntl * 8 + 2 * c);
            #pragma unroll
            for (int s = 0; s < 2; s++) {
                int row = (sp * 2 + s) * 16 + r;
                *(__half2*)(ffh + row * STH_FF + gpos) =
                    __floats2half2_rn(fmaxf(a1a[j][s][0] + bb.x, 0.f), fmaxf(a1a[j][s][1] + bb.y, 0.f));
                *(__half2*)(ffh + (row + 8) * STH_FF + gpos) =
                    __floats2half2_rn(fmaxf(a1a[j][s][2] + bb.x, 0.f), fmaxf(a1a[j][s][3] + bb.y, 0.f));
            }
        }
    }
    __syncthreads();

    // ---- FF2: single K=512 sweep (16 k32 steps) ----
    {
        float accF2[2][2][4] = {};
        const __half* Ah = ffh + (sp * 32 + r) * STH_FF + 4 * c;
        #pragma unroll
        for (int ktp = 0; ktp < 16; ktp++) {
            uint4 bb0 = F2[((2 * q)     * 16 + ktp) * 32 + lane];
            uint4 bb1 = F2[((2 * q + 1) * 16 + ktp) * 32 + lane];
            #pragma unroll
            for (int s = 0; s < 2; s++) {
                const __half* As = Ah + s * 16 * STH_FF;
                #pragma unroll
                for (int kk = 0; kk < 2; kk++) {
                    int g = (ktp * 2 + kk) * 16;
                    uint2 lo = *(const uint2*)(As + g);
                    uint2 hi = *(const uint2*)(As + 8 * STH_FF + g);
                    mma16(accF2[0][s], lo.x, hi.x, lo.y, hi.y, kk ? bb0.z : bb0.x, kk ? bb0.w : bb0.y);
                    mma16(accF2[1][s], lo.x, hi.x, lo.y, hi.y, kk ? bb1.z : bb1.x, kk ? bb1.w : bb1.y);
                }
            }
        }
        __syncthreads();
        #pragma unroll
        for (int j = 0; j < 2; j++) {
            int n0 = (2 * q + j) * 8 + 2 * c;
            float2 bb = *(const float2*)(bf2 + n0);
            #pragma unroll
            for (int s = 0; s < 2; s++) {
                int row = (sp * 2 + s) * 16 + r;
                *(float2*)(o + row * ST_X + n0)       = make_float2(accF2[j][s][0] + bb.x, accF2[j][s][1] + bb.y);
                *(float2*)(o + (row + 8) * ST_X + n0) = make_float2(accF2[j][s][2] + bb.x, accF2[j][s][3] + bb.y);
            }
        }
    }
    __syncthreads();

    lnorm64(o, h, g2, b2v, resid, dstF, dstH, gdst);
    __syncthreads();
}

__global__ void __launch_bounds__(NT, 1)
encoder_kernel(const float* __restrict__ b1_bo, const float* __restrict__ b1_bf1,
               const float* __restrict__ b1_bf2,
               const float* __restrict__ b1_g1, const float* __restrict__ b1_b1,
               const float* __restrict__ b1_g2, const float* __restrict__ b1_b2,
               const float* __restrict__ b2_bo, const float* __restrict__ b2_bf1,
               const float* __restrict__ b2_bf2,
               const float* __restrict__ b2_g1, const float* __restrict__ b2_b1,
               const float* __restrict__ b2_g2, const float* __restrict__ b2_b2) {
    extern __shared__ float arena[];
    const int b = blockIdx.x >> 5;
    const int t0 = (blockIdx.x & 31) << 2;

    __half* hb  = (__half*)(arena + S_HALF);
    __half* x1h = hb + H_X1H;
    float*  x1  = arena + S_X1;
    const __half* Pbase = g_P + (long)b * 128 * 1152;
    __half* gx2 = g_x2 + (long)(b * 128 + t0) * 2048;

    const unsigned* G = g_wfrag;
    run_block<true>(arena, nullptr, Pbase, t0, nullptr,
                    nullptr, nullptr, nullptr, (const uint4*)(G + WFO1),
                    (const uint4*)(G + WF11), (const uint4*)(G + WF21),
                    b1_bo, b1_bf1, b1_bf2, b1_g1, b1_b1, b1_g2, b1_b2,
                    x1, x1h, nullptr);

    run_block<false>(arena, x1h, nullptr, 0, x1,
                     (const uint4*)(G + WFQ2), (const uint4*)(G + WFK2),
                     (const uint4*)(G + WFV2), (const uint4*)(G + WFO2),
                     (const uint4*)(G + WF12), (const uint4*)(G + WF22),
                     b2_bo, b2_bf1, b2_bf2, b2_g1, b2_b1, b2_g2, b2_b2,
                     nullptr, nullptr, gx2);
}

// ================= kernel 2: final projection GEMM (32-row m-tiles) ========
#define STH_F 2064
__global__ void __launch_bounds__(256)
final_kernel(const float* __restrict__ bf, float* __restrict__ out) {
    extern __shared__ __half fs[];
    const int tid = threadIdx.x;
    const int warp = tid >> 5, lane = tid & 31;
    const int r = lane >> 2, c = lane & 3;
    const int seq0 = blockIdx.x * 32;

    // stage A tile (32 x 2048) into smem at stride 2064
    for (int i = tid; i < 8192; i += 256) {
        int row = i >> 8, cg = i & 255;
        const uint4* src = (const uint4*)(g_x2 + (long)(seq0 + row) * 2048) + cg;
        *((uint4*)(fs + row * STH_F) + cg) = *src;
    }
    __syncthreads();

    const uint4* Fw = (const uint4*)(g_wfrag + WFWF);
    float acc[2][2][4] = {};   // [mt][nt][frag]
    for (int ktg = 0; ktg < 64; ktg++) {
        uint4 bb0 = Fw[((2 * warp)     * 64 + ktg) * 32 + lane];
        uint4 bb1 = Fw[((2 * warp + 1) * 64 + ktg) * 32 + lane];
        #pragma unroll
        for (int mt = 0; mt < 2; mt++) {
            const __half* Ah = fs + (mt * 16 + r) * STH_F + 4 * c;
            #pragma unroll
            for (int kk = 0; kk < 2; kk++) {
                int g = (ktg * 2 + kk) * 16;
                uint2 lo = *(const uint2*)(Ah + g);
                uint2 hi = *(const uint2*)(Ah + 8 * STH_F + g);
                mma16(acc[mt][0], lo.x, hi.x, lo.y, hi.y, kk ? bb0.z : bb0.x, kk ? bb0.w : bb0.y);
                mma16(acc[mt][1], lo.x, hi.x, lo.y, hi.y, kk ? bb1.z : bb1.x, kk ? bb1.w : bb1.y);
            }
        }
    }
    const int b = seq0 >> 7;
    const int tbase = seq0 & 127;
    #pragma unroll
    for (int mt = 0; mt < 2; mt++) {
        #pragma unroll
        for (int j = 0; j < 2; j++) {
            int n0 = (2 * warp + j) * 8 + 2 * c;
            float bf0 = bf[n0], bf1 = bf[n0 + 1];
            int t = tbase + mt * 16 + r;
            out[((long)b * 128 + n0)     * 128 + t]     = acc[mt][j][0] + bf0;
            out[((long)b * 128 + n0 + 1) * 128 + t]     = acc[mt][j][1] + bf1;
            out[((long)b * 128 + n0)     * 128 + t + 8] = acc[mt][j][2] + bf0;
            out[((long)b * 128 + n0 + 1) * 128 + t + 8] = acc[mt][j][3] + bf1;
        }
    }
}

extern "C" void kernel_launch(void* const* d_in, const int* in_sizes, int n_in,
                              void* d_out, int out_size) {
    (void)in_sizes; (void)n_in; (void)out_size;
    const float* p[30];
    for (int i = 0; i < 30; i++) p[i] = (const float*)d_in[i];

    static bool attr_set = false;
    if (!attr_set) {
        cudaFuncSetAttribute(qkv1_kernel, cudaFuncAttributeMaxDynamicSharedMemorySize,
                             128 * STH_P * (int)sizeof(__half));
        cudaFuncSetAttribute(encoder_kernel, cudaFuncAttributeMaxDynamicSharedMemorySize,
                             ARENA_FLOATS * (int)sizeof(float));
        cudaFuncSetAttribute(final_kernel, cudaFuncAttributeMaxDynamicSharedMemorySize,
                             32 * STH_F * (int)sizeof(__half));
        attr_set = true;
    }

    prep_weights<<<(FRAG_TOTAL + 255) / 256, 256>>>(
        p[2], p[3], p[4], p[5], p[7], p[9],
        p[15], p[16], p[17], p[18], p[20], p[22], p[28]);

    qkv1_kernel<<<64, NT, 128 * STH_P * sizeof(__half)>>>(p[0], p[1]);

    encoder_kernel<<<2048, NT, ARENA_FLOATS * sizeof(float)>>>(
        p[6],  p[8],  p[10], p[11], p[12], p[13], p[14],
        p[19], p[21], p[23], p[24], p[25], p[26], p[27]);

    final_kernel<<<256, 256, 32 * STH_F * sizeof(__half)>>>(p[29], (float*)d_out);
}

// round 12
// speedup vs baseline: 7.8666x; 1.0517x over previous
#include <cuda_runtime.h>
#include <cuda_fp16.h>

#define NT 512

// ---------------- fp16 fragment-linear weight scratch ----------------
// m16n8k16 f16 B-fragments, k32 (2 k16 tiles) packed per uint4:
//   uint index = (nt*KTP + ktp)*128 + lane*4 + kk*2 + reg   (each uint = half2)
//   kbase = (2*ktp+kk)*16 + reg*8 + 2*(lane&3) ; n = nt*8 + (lane>>2)
#define FRAG_TOTAL 346112
__device__ __align__(16) unsigned int g_wfrag[FRAG_TOTAL];

#define WFQ1 0
#define WFK1 14336
#define WFV1 28672
#define WFO1 43008
#define WF11 51200
#define WF21 83968
#define WFQ2 116736
#define WFK2 124928
#define WFV2 133120
#define WFO2 141312
#define WF12 149504
#define WF22 182272
#define WFWF 215040

// big intermediates (L2-resident)
__device__ __align__(16) __half g_P[8192 * 1152];    // block1 qkv projections per (b,tc)
__device__ __align__(16) __half g_x2[8192 * 2048];   // x2 flat, permuted fragment layout

__global__ void prep_weights(const float* __restrict__ q1, const float* __restrict__ k1,
                             const float* __restrict__ v1, const float* __restrict__ o1,
                             const float* __restrict__ f11, const float* __restrict__ f21,
                             const float* __restrict__ q2, const float* __restrict__ k2,
                             const float* __restrict__ v2, const float* __restrict__ o2,
                             const float* __restrict__ f12, const float* __restrict__ f22,
                             const float* __restrict__ wf) {
    int e = blockIdx.x * blockDim.x + threadIdx.x;
    if (e >= FRAG_TOTAL) return;
    const int offs[14] = {0,14336,28672,43008,51200,83968,116736,124928,133120,
                          141312,149504,182272,215040,346112};
    const int Kr[13] = {196,196,196,128,128,512,128,128,128,128,128,512,2048};
    const int Nn[13] = {128,128,128,128,512,128,128,128,128,128,512,128,128};
    int m = 0;
    while (e >= offs[m + 1]) m++;
    const float* W =
        m==0?q1: m==1?k1: m==2?v1: m==3?o1: m==4?f11: m==5?f21:
        m==6?q2: m==7?k2: m==8?v2: m==9?o2: m==10?f12: m==11?f22: wf;
    int l = e - offs[m];
    int N = Nn[m], K = Kr[m];
    int KTPm = (offs[m + 1] - offs[m]) / (16 * N);
    int blk = l >> 7, li = l & 127;
    int lane = li >> 2, kk = (li >> 1) & 1, reg = li & 1;
    int nt = blk / KTPm, ktp = blk - nt * KTPm;
    int kbase = (2 * ktp + kk) * 16 + reg * 8 + 2 * (lane & 3);
    int n = nt * 8 + (lane >> 2);
    float wa = (kbase     < K) ? W[(long)kbase * N + n] : 0.f;
    float wb = (kbase + 1 < K) ? W[(long)(kbase + 1) * N + n] : 0.f;
    __half2 h2 = __floats2half2_rn(wa, wb);
    g_wfrag[e] = *reinterpret_cast<unsigned int*>(&h2);
}

// ---------------- layout helpers ----------------
__device__ __forceinline__ int permc(int l) {
    return (l < 8) ? ((l >> 1) * 4 + (l & 1)) : (((l - 8) >> 1) * 4 + 2 + (l & 1));
}
__device__ __forceinline__ int pcol(int col) {
    return (col >> 4) * 16 + permc(col & 15);
}

__device__ __forceinline__ void mma16(float* d, unsigned a0, unsigned a1,
                                      unsigned a2, unsigned a3,
                                      unsigned b0, unsigned b1) {
    asm volatile("mma.sync.aligned.m16n8k16.row.col.f32.f16.f16.f32 "
                 "{%0,%1,%2,%3}, {%4,%5,%6,%7}, {%8,%9}, {%0,%1,%2,%3};"
                 : "+f"(d[0]), "+f"(d[1]), "+f"(d[2]), "+f"(d[3])
                 : "r"(a0), "r"(a1), "r"(a2), "r"(a3), "r"(b0), "r"(b1));
}

// ================= kernel 0: per-timestep QKV projections for block 1 ======
// grid 128: blockIdx.x = b*2 + half; each CTA handles 64 timesteps.
#define STH_P 240
__global__ void __launch_bounds__(NT, 1)
qkv1_kernel(const float* __restrict__ enc, const float* __restrict__ off) {
    extern __shared__ __half xsm[];
    const int tid = threadIdx.x;
    const int warp = tid >> 5, lane = tid & 31;
    const int r = lane >> 2, c = lane & 3;
    const int b = blockIdx.x >> 1;
    const int th = (blockIdx.x & 1) * 64;   // timestep base

    // stage 64 rows x 224 cols (permuted), coalesced over t
    for (int i = tid; i < 224 * 64; i += NT) {
        int cc = i >> 6, tl = i & 63;
        int t = th + tl;
        float val = 0.f;
        if (cc < 112)      val = enc[((long)b * 112 + cc) * 128 + t];
        else if (cc < 196) val = off[b * 84 + (cc - 112)];
        xsm[tl * STH_P + pcol(cc)] = __float2half_rn(val);
    }
    __syncthreads();

    const uint4* Fq = (const uint4*)(g_wfrag + WFQ1);
    const uint4* Fk = (const uint4*)(g_wfrag + WFK1);
    const uint4* Fv = (const uint4*)(g_wfrag + WFV1);
    const int n0 = warp * 8 + 2 * c;
    __half* Pb = g_P + (long)b * 128 * 1152;

    for (int mt = 0; mt < 4; mt++) {
        float aq[4] = {}, ak[4] = {}, av[4] = {};
        const __half* Ah = xsm + (mt * 16 + r) * STH_P + 4 * c;
        #pragma unroll
        for (int ktp = 0; ktp < 7; ktp++) {
            uint4 bq = Fq[(warp * 7 + ktp) * 32 + lane];
            uint4 bk = Fk[(warp * 7 + ktp) * 32 + lane];
            uint4 bv = Fv[(warp * 7 + ktp) * 32 + lane];
            #pragma unroll
            for (int kk = 0; kk < 2; kk++) {
                int g = (ktp * 2 + kk) * 16;
                uint2 lo = *(const uint2*)(Ah + g);
                uint2 hi = *(const uint2*)(Ah + 8 * STH_P + g);
                mma16(aq, lo.x, hi.x, lo.y, hi.y, kk ? bq.z : bq.x, kk ? bq.w : bq.y);
                mma16(ak, lo.x, hi.x, lo.y, hi.y, kk ? bk.z : bk.x, kk ? bk.w : bk.y);
                mma16(av, lo.x, hi.x, lo.y, hi.y, kk ? bv.z : bv.x, kk ? bv.w : bv.y);
            }
        }
        int row0 = th + mt * 16 + r;
        __half* P0 = Pb + (long)row0 * 1152 + n0;
        __half* P1 = Pb + (long)(row0 + 8) * 1152 + n0;
        *(__half2*)(P0)       = __floats2half2_rn(aq[0], aq[1]);
        *(__half2*)(P1)       = __floats2half2_rn(aq[2], aq[3]);
        *(__half2*)(P0 + 128) = __floats2half2_rn(ak[0], ak[1]);
        *(__half2*)(P1 + 128) = __floats2half2_rn(ak[2], ak[3]);
        *(__half2*)(P0 + 256) = __floats2half2_rn(av[0], av[1]);
        *(__half2*)(P1 + 256) = __floats2half2_rn(av[2], av[3]);
    }
}

// ---------------- encoder shared arena ----------------
#define ST_X    136
#define STH_X   144
#define STH_FF  528     // full-width ff buffer (64 x 512 cols)
#define S_O     0
#define S_H     8704
#define S_X1    17408
#define S_HALF  26112
#define H_OH    0
#define H_HH    9216
#define H_X1H   18432
#define H_FFH   27648   // 64 x 528 halves = 33792
#define ARENA_FLOATS 56832   // = 227,328 bytes

__device__ __forceinline__ void warp_reduce2(float& s, float& s2) {
    #pragma unroll
    for (int off = 16; off; off >>= 1) {
        s  += __shfl_xor_sync(0xffffffffu, s,  off);
        s2 += __shfl_xor_sync(0xffffffffu, s2, off);
    }
}

// LayerNorm over 64 rows x 128 cols.
__device__ void lnorm64(const float* __restrict__ src, const float* __restrict__ resid,
                        const float* __restrict__ g, const float* __restrict__ bta,
                        const float* __restrict__ dst_add,
                        float* __restrict__ dstF, __half* __restrict__ dstH,
                        __half* __restrict__ gdst) {
    int warp = threadIdx.x >> 5, lane = threadIdx.x & 31;
    #pragma unroll
    for (int rr = 0; rr < 4; rr++) {
        int row = warp + rr * 16;
        float v[4]; float s = 0.f, s2 = 0.f;
        #pragma unroll
        for (int i = 0; i < 4; i++) {
            int col = lane + 32 * i;
            float x = src[row * ST_X + col];
            if (resid) x += resid[row * ST_X + col];
            v[i] = x; s += x; s2 += x * x;
        }
        warp_reduce2(s, s2);
        float m   = s * (1.f / 128.f);
        float var = fmaxf(s2 * (1.f / 128.f) - m * m, 0.f);
        float inv = rsqrtf(var + 1e-5f);
        #pragma unroll
        for (int i = 0; i < 4; i++) {
            int col = lane + 32 * i;
            float val = (v[i] - m) * inv * g[col] + bta[col];
            if (dst_add) val += dst_add[row * ST_X + col];
            if (dstF) dstF[row * ST_X + col] = val;
            if (dstH) dstH[row * STH_X + pcol(col)] = __float2half_rn(val);
            if (gdst) {
                int sq = row >> 4, w = row & 15;
                gdst[(long)sq * 2048 + pcol(w * 128 + col)] = __float2half_rn(val);
            }
        }
    }
}

// One transformer block over 4 sequences. GATHER: q/k/v loaded from g_P.
template<bool GATHER>
__device__ void run_block(float* arena, const __half* __restrict__ Xh,
                          const __half* __restrict__ Pbase, int t0,
                          const float* __restrict__ resid,
                          const uint4* __restrict__ Fq, const uint4* __restrict__ Fk,
                          const uint4* __restrict__ Fv, const uint4* __restrict__ Fo,
                          const uint4* __restrict__ F1, const uint4* __restrict__ F2,
                          const float* __restrict__ bo, const float* __restrict__ bf1,
                          const float* __restrict__ bf2,
                          const float* __restrict__ g1, const float* __restrict__ b1v,
                          const float* __restrict__ g2, const float* __restrict__ b2v,
                          float* __restrict__ dstF, __half* __restrict__ dstH,
                          __half* __restrict__ gdst) {
    const int warp = threadIdx.x >> 5, lane = threadIdx.x & 31;
    const int r = lane >> 2, c = lane & 3;
    float*  o   = arena + S_O;
    float*  h   = arena + S_H;
    __half* hb  = (__half*)(arena + S_HALF);
    __half* oh  = hb + H_OH;
    __half* hh  = hb + H_HH;
    __half* ffh = hb + H_FFH;

    // ---- QKV + register attention ----
    {
        float aq[4][4], ak[4][4], av[4][4];
        if (GATHER) {
            const int n0 = warp * 8 + 2 * c;
            #pragma unroll
            for (int s = 0; s < 4; s++) {
                int t = t0 + s;
                int tcA = min(max(t + r - 8, 0), 127);
                int tcB = min(max(t + r, 0), 127);
                const __half* Pa = Pbase + (long)tcA * 1152 + n0;
                const __half* Pc = Pbase + (long)tcB * 1152 + n0;
                float2 f;
                f = __half22float2(*(const __half2*)(Pa));        aq[s][0]=f.x; aq[s][1]=f.y;
                f = __half22float2(*(const __half2*)(Pc));        aq[s][2]=f.x; aq[s][3]=f.y;
                f = __half22float2(*(const __half2*)(Pa + 128));  ak[s][0]=f.x; ak[s][1]=f.y;
                f = __half22float2(*(const __half2*)(Pc + 128));  ak[s][2]=f.x; ak[s][3]=f.y;
                f = __half22float2(*(const __half2*)(Pa + 256));  av[s][0]=f.x; av[s][1]=f.y;
                f = __half22float2(*(const __half2*)(Pc + 256));  av[s][2]=f.x; av[s][3]=f.y;
            }
        } else {
            #pragma unroll
            for (int s = 0; s < 4; s++)
                #pragma unroll
                for (int i = 0; i < 4; i++) { aq[s][i]=0.f; ak[s][i]=0.f; av[s][i]=0.f; }
            const __half* Ah = Xh + r * STH_X + 4 * c;
            #pragma unroll
            for (int ktp = 0; ktp < 4; ktp++) {
                uint4 bq = Fq[(warp * 4 + ktp) * 32 + lane];
                uint4 bk = Fk[(warp * 4 + ktp) * 32 + lane];
                uint4 bv = Fv[(warp * 4 + ktp) * 32 + lane];
                #pragma unroll
                for (int s = 0; s < 4; s++) {
                    const __half* As = Ah + s * 16 * STH_X;
                    #pragma unroll
                    for (int kk = 0; kk < 2; kk++) {
                        int g = (ktp * 2 + kk) * 16;
                        uint2 lo = *(const uint2*)(As + g);
                        uint2 hi = *(const uint2*)(As + 8 * STH_X + g);
                        mma16(aq[s], lo.x, hi.x, lo.y, hi.y, kk ? bq.z : bq.x, kk ? bq.w : bq.y);
                        mma16(ak[s], lo.x, hi.x, lo.y, hi.y, kk ? bk.z : bk.x, kk ? bk.w : bk.y);
                        mma16(av[s], lo.x, hi.x, lo.y, hi.y, kk ? bv.z : bv.x, kk ? bv.w : bv.y);
                    }
                }
            }
        }
        const float scale = 0.70710678118654752f;
        int gpos = (warp >> 1) * 16 + 4 * c + 2 * (warp & 1);
        #pragma unroll
        for (int s = 0; s < 4; s++) {
            float sumA = 0.f, sumB = 0.f;
            float oA0 = 0.f, oA1 = 0.f, oB0 = 0.f, oB1 = 0.f;
            #pragma unroll
            for (int rp = 0; rp < 8; rp++) {
                int src = rp * 4 + c;
                float k00 = __shfl_sync(0xffffffffu, ak[s][0], src);
                float k01 = __shfl_sync(0xffffffffu, ak[s][1], src);
                float k10 = __shfl_sync(0xffffffffu, ak[s][2], src);
                float k11 = __shfl_sync(0xffffffffu, ak[s][3], src);
                float v00 = __shfl_sync(0xffffffffu, av[s][0], src);
                float v01 = __shfl_sync(0xffffffffu, av[s][1], src);
                float v10 = __shfl_sync(0xffffffffu, av[s][2], src);
                float v11 = __shfl_sync(0xffffffffu, av[s][3], src);
                float eA0 = __expf((aq[s][0] * k00 + aq[s][1] * k01) * scale);
                float eA1 = __expf((aq[s][0] * k10 + aq[s][1] * k11) * scale);
                float eB0 = __expf((aq[s][2] * k00 + aq[s][3] * k01) * scale);
                float eB1 = __expf((aq[s][2] * k10 + aq[s][3] * k11) * scale);
                sumA += eA0 + eA1; sumB += eB0 + eB1;
                oA0 += eA0 * v00 + eA1 * v10; oA1 += eA0 * v01 + eA1 * v11;
                oB0 += eB0 * v00 + eB1 * v10; oB1 += eB0 * v01 + eB1 * v11;
            }
            float iA = 1.f / sumA, iB = 1.f / sumB;
            *(__half2*)(oh + (s * 16 + r) * STH_X + gpos)     = __floats2half2_rn(oA0 * iA, oA1 * iA);
            *(__half2*)(oh + (s * 16 + r + 8) * STH_X + gpos) = __floats2half2_rn(oB0 * iB, oB1 * iB);
        }
    }
    __syncthreads();

    const int sp = warp >> 3, q = warp & 7;

    // ---- WO: warp = (2 nt, 2 seq), KTP=4 ----
    {
        float acc[2][2][4] = {};
        const __half* Ah = oh + (sp * 32 + r) * STH_X + 4 * c;
        #pragma unroll
        for (int ktp = 0; ktp < 4; ktp++) {
            uint4 bb0 = Fo[((2 * q)     * 4 + ktp) * 32 + lane];
            uint4 bb1 = Fo[((2 * q + 1) * 4 + ktp) * 32 + lane];
            #pragma unroll
            for (int s = 0; s < 2; s++) {
                const __half* As = Ah + s * 16 * STH_X;
                #pragma unroll
                for (int kk = 0; kk < 2; kk++) {
                    int g = (ktp * 2 + kk) * 16;
                    uint2 lo = *(const uint2*)(As + g);
                    uint2 hi = *(const uint2*)(As + 8 * STH_X + g);
                    mma16(acc[0][s], lo.x, hi.x, lo.y, hi.y, kk ? bb0.z : bb0.x, kk ? bb0.w : bb0.y);
                    mma16(acc[1][s], lo.x, hi.x, lo.y, hi.y, kk ? bb1.z : bb1.x, kk ? bb1.w : bb1.y);
                }
            }
        }
        #pragma unroll
        for (int j = 0; j < 2; j++) {
            int n0 = (2 * q + j) * 8 + 2 * c;
            float2 bb = *(const float2*)(bo + n0);
            #pragma unroll
            for (int s = 0; s < 2; s++) {
                int row = (sp * 2 + s) * 16 + r;
                *(float2*)(h + row * ST_X + n0)       = make_float2(acc[j][s][0] + bb.x, acc[j][s][1] + bb.y);
                *(float2*)(h + (row + 8) * ST_X + n0) = make_float2(acc[j][s][2] + bb.x, acc[j][s][3] + bb.y);
            }
        }
    }
    __syncthreads();

    lnorm64(h, resid, g1, b1v, nullptr, h, hh, nullptr);
    __syncthreads();

    // ---- FF1: both N-halves into full-width ffh, ONE sync ----
    #pragma unroll
    for (int half = 0; half < 2; half++) {
        float a1a[4][2][4] = {};
        const __half* Ah = hh + (sp * 32 + r) * STH_X + 4 * c;
        #pragma unroll
        for (int ktp = 0; ktp < 4; ktp++) {
            uint4 bb[4];
            #pragma unroll
            for (int j = 0; j < 4; j++)
                bb[j] = F1[((half * 32 + q * 4 + j) * 4 + ktp) * 32 + lane];
            #pragma unroll
            for (int s = 0; s < 2; s++) {
                const __half* As = Ah + s * 16 * STH_X;
                #pragma unroll
                for (int kk = 0; kk < 2; kk++) {
                    int g = (ktp * 2 + kk) * 16;
                    uint2 lo = *(const uint2*)(As + g);
                    uint2 hi = *(const uint2*)(As + 8 * STH_X + g);
                    #pragma unroll
                    for (int j = 0; j < 4; j++)
                        mma16(a1a[j][s], lo.x, hi.x, lo.y, hi.y,
                              kk ? bb[j].z : bb[j].x, kk ? bb[j].w : bb[j].y);
                }
            }
        }
        #pragma unroll
        for (int j = 0; j < 4; j++) {
            int ntl = q * 4 + j;
            int gpos = half * 256 + (ntl >> 1) * 16 + 4 * c + 2 * (ntl & 1);
            float2 bb = *(const float2*)(bf1 + half * 256 + ntl * 8 + 2 * c);
            #pragma unroll
            for (int s = 0; s < 2; s++) {
                int row = (sp * 2 + s) * 16 + r;
                *(__half2*)(ffh + row * STH_FF + gpos) =
                    __floats2half2_rn(fmaxf(a1a[j][s][0] + bb.x, 0.f), fmaxf(a1a[j][s][1] + bb.y, 0.f));
                *(__half2*)(ffh + (row + 8) * STH_FF + gpos) =
                    __floats2half2_rn(fmaxf(a1a[j][s][2] + bb.x, 0.f), fmaxf(a1a[j][s][3] + bb.y, 0.f));
            }
        }
    }
    __syncthreads();

    // ---- FF2: single K=512 sweep (16 k32 steps) ----
    {
        float accF2[2][2][4] = {};
        const __half* Ah = ffh + (sp * 32 + r) * STH_FF + 4 * c;
        #pragma unroll
        for (int ktp = 0; ktp < 16; ktp++) {
            uint4 bb0 = F2[((2 * q)     * 16 + ktp) * 32 + lane];
            uint4 bb1 = F2[((2 * q + 1) * 16 + ktp) * 32 + lane];
            #pragma unroll
            for (int s = 0; s < 2; s++) {
                const __half* As = Ah + s * 16 * STH_FF;
                #pragma unroll
                for (int kk = 0; kk < 2; kk++) {
                    int g = (ktp * 2 + kk) * 16;
                    uint2 lo = *(const uint2*)(As + g);
                    uint2 hi = *(const uint2*)(As + 8 * STH_FF + g);
                    mma16(accF2[0][s], lo.x, hi.x, lo.y, hi.y, kk ? bb0.z : bb0.x, kk ? bb0.w : bb0.y);
                    mma16(accF2[1][s], lo.x, hi.x, lo.y, hi.y, kk ? bb1.z : bb1.x, kk ? bb1.w : bb1.y);
                }
            }
        }
        __syncthreads();
        #pragma unroll
        for (int j = 0; j < 2; j++) {
            int n0 = (2 * q + j) * 8 + 2 * c;
            float2 bb = *(const float2*)(bf2 + n0);
            #pragma unroll
            for (int s = 0; s < 2; s++) {
                int row = (sp * 2 + s) * 16 + r;
                *(float2*)(o + row * ST_X + n0)       = make_float2(accF2[j][s][0] + bb.x, accF2[j][s][1] + bb.y);
                *(float2*)(o + (row + 8) * ST_X + n0) = make_float2(accF2[j][s][2] + bb.x, accF2[j][s][3] + bb.y);
            }
        }
    }
    __syncthreads();

    lnorm64(o, h, g2, b2v, resid, dstF, dstH, gdst);
    __syncthreads();
}

__global__ void __launch_bounds__(NT, 1)
encoder_kernel(const float* __restrict__ b1_bo, const float* __restrict__ b1_bf1,
               const float* __restrict__ b1_bf2,
               const float* __restrict__ b1_g1, const float* __restrict__ b1_b1,
               const float* __restrict__ b1_g2, const float* __restrict__ b1_b2,
               const float* __restrict__ b2_bo, const float* __restrict__ b2_bf1,
               const float* __restrict__ b2_bf2,
               const float* __restrict__ b2_g1, const float* __restrict__ b2_b1,
               const float* __restrict__ b2_g2, const float* __restrict__ b2_b2) {
    extern __shared__ float arena[];
    const int b = blockIdx.x >> 5;
    const int t0 = (blockIdx.x & 31) << 2;

    __half* hb  = (__half*)(arena + S_HALF);
    __half* x1h = hb + H_X1H;
    float*  x1  = arena + S_X1;
    const __half* Pbase = g_P + (long)b * 128 * 1152;
    __half* gx2 = g_x2 + (long)(b * 128 + t0) * 2048;

    const unsigned* G = g_wfrag;
    run_block<true>(arena, nullptr, Pbase, t0, nullptr,
                    nullptr, nullptr, nullptr, (const uint4*)(G + WFO1),
                    (const uint4*)(G + WF11), (const uint4*)(G + WF21),
                    b1_bo, b1_bf1, b1_bf2, b1_g1, b1_b1, b1_g2, b1_b2,
                    x1, x1h, nullptr);

    run_block<false>(arena, x1h, nullptr, 0, x1,
                     (const uint4*)(G + WFQ2), (const uint4*)(G + WFK2),
                     (const uint4*)(G + WFV2), (const uint4*)(G + WFO2),
                     (const uint4*)(G + WF12), (const uint4*)(G + WF22),
                     b2_bo, b2_bf1, b2_bf2, b2_g1, b2_b1, b2_g2, b2_b2,
                     nullptr, nullptr, gx2);
}

// ================= kernel 2: final projection GEMM =========================
// grid 512 (16-row m-tiles), 512 threads: warp = (kh = K-half, q = nt pair).
// kh=1 warps store partials to smem; kh=0 reduce + write.
#define STH_F 2064
#define FIN_SMEM (16 * STH_F * 2 + 2048 * 4)   // A tile + reduce scratch
__global__ void __launch_bounds__(512)
final_kernel(const float* __restrict__ bf, float* __restrict__ out) {
    extern __shared__ __half fs[];
    float* scr = (float*)(fs + 16 * STH_F);   // 2048 floats
    const int tid = threadIdx.x;
    const int warp = tid >> 5, lane = tid & 31;
    const int r = lane >> 2, c = lane & 3;
    const int kh = warp >> 3, q = warp & 7;
    const int seq0 = blockIdx.x * 16;

    // stage A tile (16 x 2048) into smem at stride 2064
    for (int i = tid; i < 4096; i += 512) {
        int row = i >> 8, cg = i & 255;
        const uint4* src = (const uint4*)(g_x2 + (long)(seq0 + row) * 2048) + cg;
        *((uint4*)(fs + row * STH_F) + cg) = *src;
    }
    __syncthreads();

    const uint4* Fw = (const uint4*)(g_wfrag + WFWF);
    float acc[2][4] = {};
    const __half* Ah = fs + r * STH_F + 4 * c;
    #pragma unroll 4
    for (int ktl = 0; ktl < 32; ktl++) {
        int ktg = kh * 32 + ktl;
        uint4 bb0 = Fw[((2 * q)     * 64 + ktg) * 32 + lane];
        uint4 bb1 = Fw[((2 * q + 1) * 64 + ktg) * 32 + lane];
        #pragma unroll
        for (int kk = 0; kk < 2; kk++) {
            int g = (ktg * 2 + kk) * 16;
            uint2 lo = *(const uint2*)(Ah + g);
            uint2 hi = *(const uint2*)(Ah + 8 * STH_F + g);
            mma16(acc[0], lo.x, hi.x, lo.y, hi.y, kk ? bb0.z : bb0.x, kk ? bb0.w : bb0.y);
            mma16(acc[1], lo.x, hi.x, lo.y, hi.y, kk ? bb1.z : bb1.x, kk ? bb1.w : bb1.y);
        }
    }
    if (kh == 1) {
        #pragma unroll
        for (int j = 0; j < 2; j++) {
            float* sp = scr + ((2 * q + j) * 32 + lane) * 4;
            sp[0] = acc[j][0]; sp[1] = acc[j][1]; sp[2] = acc[j][2]; sp[3] = acc[j][3];
        }
    }
    __syncthreads();
    if (kh == 0) {
        const int b = seq0 >> 7;
        const int tbase = seq0 & 127;
        #pragma unroll
        for (int j = 0; j < 2; j++) {
            const float* sp = scr + ((2 * q + j) * 32 + lane) * 4;
            int n0 = (2 * q + j) * 8 + 2 * c;
            float bf0 = bf[n0], bf1 = bf[n0 + 1];
            out[((long)b * 128 + n0)     * 128 + tbase + r]     = acc[j][0] + sp[0] + bf0;
            out[((long)b * 128 + n0 + 1) * 128 + tbase + r]     = acc[j][1] + sp[1] + bf1;
            out[((long)b * 128 + n0)     * 128 + tbase + r + 8] = acc[j][2] + sp[2] + bf0;
            out[((long)b * 128 + n0 + 1) * 128 + tbase + r + 8] = acc[j][3] + sp[3] + bf1;
        }
    }
}

extern "C" void kernel_launch(void* const* d_in, const int* in_sizes, int n_in,
                              void* d_out, int out_size) {
    (void)in_sizes; (void)n_in; (void)out_size;
    const float* p[30];
    for (int i = 0; i < 30; i++) p[i] = (const float*)d_in[i];

    static bool attr_set = false;
    if (!attr_set) {
        cudaFuncSetAttribute(qkv1_kernel, cudaFuncAttributeMaxDynamicSharedMemorySize,
                             64 * STH_P * (int)sizeof(__half));
        cudaFuncSetAttribute(encoder_kernel, cudaFuncAttributeMaxDynamicSharedMemorySize,
                             ARENA_FLOATS * (int)sizeof(float));
        cudaFuncSetAttribute(final_kernel, cudaFuncAttributeMaxDynamicSharedMemorySize,
                             FIN_SMEM);
        attr_set = true;
    }

    prep_weights<<<(FRAG_TOTAL + 255) / 256, 256>>>(
        p[2], p[3], p[4], p[5], p[7], p[9],
        p[15], p[16], p[17], p[18], p[20], p[22], p[28]);

    qkv1_kernel<<<128, NT, 64 * STH_P * sizeof(__half)>>>(p[0], p[1]);

    encoder_kernel<<<2048, NT, ARENA_FLOATS * sizeof(float)>>>(
        p[6],  p[8],  p[10], p[11], p[12], p[13], p[14],
        p[19], p[21], p[23], p[24], p[25], p[26], p[27]);

    final_kernel<<<512, 512, FIN_SMEM>>>(p[29], (float*)d_out);
}